// round 1
// baseline (speedup 1.0000x reference)
#include <cuda_runtime.h>

#define BATCH 2
#define SEQ   2048
#define DIMC  1024
#define NHEAD 16
#define HD    64
#define SCALE 0.125f            // 64^-0.5

#define M_TOT (BATCH*SEQ)       // 4096
#define QKV_N (3*DIMC)          // 3072

// Scratch (allocation-free rule: __device__ globals)
__device__ float g_qkv[(size_t)M_TOT * QKV_N];   // [B,N,3,H,HD] == [4096,3072]
__device__ float g_ao [(size_t)M_TOT * DIMC];    // attention out [B,N,C]

// ---------------------------------------------------------------------------
// GEMM-NT: C[M,N] = A[M,K] * B[N,K]^T   (both row-major, K contiguous)
// 128x128x8 tile, 256 threads, 8x8 per thread with split 4+4 sub-tiles.
// Requires M,N % 128 == 0 and K % 8 == 0.
// ---------------------------------------------------------------------------
__global__ __launch_bounds__(256) void gemm_nt_128(
    const float* __restrict__ A, const float* __restrict__ B,
    float* __restrict__ C, int M, int N, int K)
{
    __shared__ float As[8][128];
    __shared__ float Bs[8][128];

    const int tid = threadIdx.x;
    const int tx = tid & 15;
    const int ty = tid >> 4;
    const int bm = blockIdx.y * 128;
    const int bn = blockIdx.x * 128;

    const int lrow = tid >> 1;          // 0..127
    const int lcol = (tid & 1) << 2;    // 0 or 4

    const float* Ap = A + (size_t)(bm + lrow) * K + lcol;
    const float* Bp = B + (size_t)(bn + lrow) * K + lcol;

    float acc[8][8];
#pragma unroll
    for (int i = 0; i < 8; i++)
#pragma unroll
        for (int j = 0; j < 8; j++) acc[i][j] = 0.f;

    for (int k0 = 0; k0 < K; k0 += 8) {
        float4 av = *(const float4*)(Ap + k0);
        float4 bv = *(const float4*)(Bp + k0);
        __syncthreads();
        As[lcol + 0][lrow] = av.x; As[lcol + 1][lrow] = av.y;
        As[lcol + 2][lrow] = av.z; As[lcol + 3][lrow] = av.w;
        Bs[lcol + 0][lrow] = bv.x; Bs[lcol + 1][lrow] = bv.y;
        Bs[lcol + 2][lrow] = bv.z; Bs[lcol + 3][lrow] = bv.w;
        __syncthreads();
#pragma unroll
        for (int kk = 0; kk < 8; kk++) {
            float ra[8], rb[8];
            *(float4*)&ra[0] = *(const float4*)&As[kk][4 * ty];
            *(float4*)&ra[4] = *(const float4*)&As[kk][64 + 4 * ty];
            *(float4*)&rb[0] = *(const float4*)&Bs[kk][4 * tx];
            *(float4*)&rb[4] = *(const float4*)&Bs[kk][64 + 4 * tx];
#pragma unroll
            for (int i = 0; i < 8; i++)
#pragma unroll
                for (int j = 0; j < 8; j++)
                    acc[i][j] += ra[i] * rb[j];
        }
    }

#pragma unroll
    for (int i = 0; i < 8; i++) {
        int r = bm + ((i < 4) ? (4 * ty + i) : (64 + 4 * ty + (i - 4)));
        float4 v0 = make_float4(acc[i][0], acc[i][1], acc[i][2], acc[i][3]);
        float4 v1 = make_float4(acc[i][4], acc[i][5], acc[i][6], acc[i][7]);
        *(float4*)&C[(size_t)r * N + bn + 4 * tx]      = v0;
        *(float4*)&C[(size_t)r * N + bn + 64 + 4 * tx] = v1;
    }
}

// ---------------------------------------------------------------------------
// Flash attention (fp32, online softmax), per-(b,h), BQ=BK=64.
// Q and K stored TRANSPOSED [d][idx] with XOR swizzle on the 16B chunk index
// (chunk ^= (row>>2)&7) -> conflict-free float4 reads AND ~2-way stores.
// K-tile smem reused for the P tile (extra barrier) -> exactly 48KB static.
// ---------------------------------------------------------------------------
__device__ __forceinline__ int swz_el(int row, int col) {
    // element (row, col) in a 64x64 tile with swizzled 4-float chunks
    return row * 64 + ((((col >> 2) ^ ((row >> 2) & 7)) << 2) | (col & 3));
}

__global__ __launch_bounds__(256) void flash_attn_kernel(
    const float* __restrict__ qkv,     // [B,N,3,H,HD]
    const float* __restrict__ head_w,  // [H]
    float* __restrict__ ao)            // [B,N,C] = [B,N,H,HD]
{
    __shared__ float Qt [64 * 64];   // Q transposed+swizzled [d][q]
    __shared__ float KPs[64 * 64];   // K transposed+swizzled [d][k]; reused as P [q][k]
    __shared__ float Vs [64 * 64];   // V natural [k][d]

    const int tid = threadIdx.x;
    const int tx = tid & 15;         // 16 cols of 4
    const int ty = tid >> 4;         // 16 rows of 4
    const int q0 = blockIdx.x * 64;
    const int h  = blockIdx.y;
    const int b  = blockIdx.z;

    // head-weight softmax (16 elems, computed redundantly per thread)
    float hw;
    {
        float mx = -1e30f;
#pragma unroll
        for (int i = 0; i < NHEAD; i++) mx = fmaxf(mx, head_w[i]);
        float ssum = 0.f;
#pragma unroll
        for (int i = 0; i < NHEAD; i++) ssum += __expf(head_w[i] - mx);
        hw = __expf(head_w[h] - mx) / ssum;
    }

    // load Q tile (transposed + swizzled)
    {
        const float* qbase = qkv + (size_t)(b * SEQ + q0) * 3 * DIMC + h * HD;
#pragma unroll
        for (int it = 0; it < 4; it++) {
            int i  = tid + it * 256;
            int r  = i >> 4;              // q row 0..63
            int c4 = (i & 15) << 2;       // d col
            float4 v = *(const float4*)(qbase + (size_t)r * 3 * DIMC + c4);
            Qt[swz_el(c4 + 0, r)] = v.x;
            Qt[swz_el(c4 + 1, r)] = v.y;
            Qt[swz_el(c4 + 2, r)] = v.z;
            Qt[swz_el(c4 + 3, r)] = v.w;
        }
    }

    float o[4][4];
    float m_r[4], l_r[4];
#pragma unroll
    for (int i = 0; i < 4; i++) {
        m_r[i] = -1e30f; l_r[i] = 0.f;
#pragma unroll
        for (int j = 0; j < 4; j++) o[i][j] = 0.f;
    }

    for (int t0 = 0; t0 < SEQ; t0 += 64) {
        __syncthreads();   // protect KPs/Vs from previous iteration's readers
        // load K (transposed+swizzled) and V (natural)
        {
            const float* kbase = qkv + ((size_t)(b * SEQ + t0) * 3 + 1) * DIMC + h * HD;
            const float* vbase = qkv + ((size_t)(b * SEQ + t0) * 3 + 2) * DIMC + h * HD;
#pragma unroll
            for (int it = 0; it < 4; it++) {
                int i  = tid + it * 256;
                int r  = i >> 4;
                int c4 = (i & 15) << 2;
                float4 kv = *(const float4*)(kbase + (size_t)r * 3 * DIMC + c4);
                KPs[swz_el(c4 + 0, r)] = kv.x;
                KPs[swz_el(c4 + 1, r)] = kv.y;
                KPs[swz_el(c4 + 2, r)] = kv.z;
                KPs[swz_el(c4 + 3, r)] = kv.w;
                float4 vv = *(const float4*)(vbase + (size_t)r * 3 * DIMC + c4);
                *(float4*)&Vs[r * 64 + c4] = vv;
            }
        }
        __syncthreads();

        // S = Q K^T  (outer-product over d; 4x4 per thread)
        float s[4][4];
#pragma unroll
        for (int i = 0; i < 4; i++)
#pragma unroll
            for (int j = 0; j < 4; j++) s[i][j] = 0.f;

#pragma unroll 8
        for (int d = 0; d < HD; d++) {
            int sw = (d >> 2) & 7;
            float4 qv = *(const float4*)&Qt [d * 64 + ((ty ^ sw) << 2)];
            float4 kv = *(const float4*)&KPs[d * 64 + ((tx ^ sw) << 2)];
            s[0][0] += qv.x * kv.x; s[0][1] += qv.x * kv.y; s[0][2] += qv.x * kv.z; s[0][3] += qv.x * kv.w;
            s[1][0] += qv.y * kv.x; s[1][1] += qv.y * kv.y; s[1][2] += qv.y * kv.z; s[1][3] += qv.y * kv.w;
            s[2][0] += qv.z * kv.x; s[2][1] += qv.z * kv.y; s[2][2] += qv.z * kv.z; s[2][3] += qv.z * kv.w;
            s[3][0] += qv.w * kv.x; s[3][1] += qv.w * kv.y; s[3][2] += qv.w * kv.z; s[3][3] += qv.w * kv.w;
        }

        // online softmax (rows of 64 keys spread over 16 lanes in a half-warp)
#pragma unroll
        for (int i = 0; i < 4; i++) {
#pragma unroll
            for (int j = 0; j < 4; j++) s[i][j] *= SCALE;
            float rm = fmaxf(fmaxf(s[i][0], s[i][1]), fmaxf(s[i][2], s[i][3]));
#pragma unroll
            for (int off = 8; off > 0; off >>= 1)
                rm = fmaxf(rm, __shfl_xor_sync(0xffffffffu, rm, off));
            float mn = fmaxf(m_r[i], rm);
            float alpha = __expf(m_r[i] - mn);
            m_r[i] = mn;
            float rs = 0.f;
#pragma unroll
            for (int j = 0; j < 4; j++) { s[i][j] = __expf(s[i][j] - mn); rs += s[i][j]; }
#pragma unroll
            for (int off = 8; off > 0; off >>= 1)
                rs += __shfl_xor_sync(0xffffffffu, rs, off);
            l_r[i] = l_r[i] * alpha + rs;
#pragma unroll
            for (int j = 0; j < 4; j++) o[i][j] *= alpha;
        }

        __syncthreads();   // everyone done reading K from KPs
        // store P into KPs (swizzled chunks, natural rows)
#pragma unroll
        for (int i = 0; i < 4; i++) {
            int r = 4 * ty + i;
            float4 pv = make_float4(s[i][0], s[i][1], s[i][2], s[i][3]);
            *(float4*)&KPs[r * 64 + ((tx ^ ((r >> 2) & 7)) << 2)] = pv;
        }
        __syncthreads();

        // O += P V   (4 rows x 4 d-cols per thread)
#pragma unroll 2
        for (int k4 = 0; k4 < 16; k4++) {
            float4 vv0 = *(const float4*)&Vs[(4 * k4 + 0) * 64 + 4 * tx];
            float4 vv1 = *(const float4*)&Vs[(4 * k4 + 1) * 64 + 4 * tx];
            float4 vv2 = *(const float4*)&Vs[(4 * k4 + 2) * 64 + 4 * tx];
            float4 vv3 = *(const float4*)&Vs[(4 * k4 + 3) * 64 + 4 * tx];
#pragma unroll
            for (int i = 0; i < 4; i++) {
                int r = 4 * ty + i;
                float4 prv = *(const float4*)&KPs[r * 64 + ((k4 ^ ((r >> 2) & 7)) << 2)];
                o[i][0] += prv.x * vv0.x; o[i][1] += prv.x * vv0.y; o[i][2] += prv.x * vv0.z; o[i][3] += prv.x * vv0.w;
                o[i][0] += prv.y * vv1.x; o[i][1] += prv.y * vv1.y; o[i][2] += prv.y * vv1.z; o[i][3] += prv.y * vv1.w;
                o[i][0] += prv.z * vv2.x; o[i][1] += prv.z * vv2.y; o[i][2] += prv.z * vv2.z; o[i][3] += prv.z * vv2.w;
                o[i][0] += prv.w * vv3.x; o[i][1] += prv.w * vv3.y; o[i][2] += prv.w * vv3.z; o[i][3] += prv.w * vv3.w;
            }
        }
    }

    // epilogue: O/l * head_weight -> ao[b, q, h*64 + d]
#pragma unroll
    for (int i = 0; i < 4; i++) {
        float inv = hw / l_r[i];
        int r = q0 + 4 * ty + i;
        float4 ov = make_float4(o[i][0] * inv, o[i][1] * inv, o[i][2] * inv, o[i][3] * inv);
        *(float4*)&ao[(size_t)(b * SEQ + r) * DIMC + h * HD + 4 * tx] = ov;
    }
}

// ---------------------------------------------------------------------------
extern "C" void kernel_launch(void* const* d_in, const int* in_sizes, int n_in,
                              void* d_out, int out_size)
{
    const float* x      = (const float*)d_in[0];
    const float* w_qkv  = (const float*)d_in[1];
    const float* w_proj = (const float*)d_in[2];
    const float* head_w = (const float*)d_in[3];
    float* out = (float*)d_out;

    float *qkv_ptr, *ao_ptr;
    cudaGetSymbolAddress((void**)&qkv_ptr, g_qkv);
    cudaGetSymbolAddress((void**)&ao_ptr,  g_ao);

    // 1) QKV projection: [4096,1024] x [3072,1024]^T -> [4096,3072]
    dim3 g1(QKV_N / 128, M_TOT / 128);
    gemm_nt_128<<<g1, 256>>>(x, w_qkv, qkv_ptr, M_TOT, QKV_N, DIMC);

    // 2) flash attention + head-weight scale -> g_ao [B,N,C]
    dim3 g2(SEQ / 64, NHEAD, BATCH);
    flash_attn_kernel<<<g2, 256>>>(qkv_ptr, head_w, ao_ptr);

    // 3) output projection: [4096,1024] x [1024,1024]^T -> out
    dim3 g3(DIMC / 128, M_TOT / 128);
    gemm_nt_128<<<g3, 256>>>(ao_ptr, w_proj, out, M_TOT, DIMC, DIMC);
}

// round 4
// speedup vs baseline: 1.1998x; 1.1998x over previous
#include <cuda_runtime.h>
#include <cuda_bf16.h>
#include <cstdint>

#define BATCH 2
#define SEQ   2048
#define DIMC  1024
#define NHEAD 16
#define HD    64
#define SCALE 0.125f            // 64^-0.5

#define M_TOT (BATCH*SEQ)       // 4096
#define QKV_N (3*DIMC)          // 3072

// Scratch (allocation-free rule: __device__ globals)
__device__ float g_qkv[(size_t)M_TOT * QKV_N];   // [B,N,3,H,HD]
__device__ float g_ao [(size_t)M_TOT * DIMC];    // attention out [B,N,C]

// ===========================================================================
// Base-target (sm_103, no 'a') tensor-core primitives: ldmatrix + mma.sync
// ===========================================================================
__device__ __forceinline__ uint32_t smem_u32(const void* p) {
    uint32_t a;
    asm("{ .reg .u64 t; cvta.to.shared.u64 t, %1; cvt.u32.u64 %0, t; }" : "=r"(a) : "l"(p));
    return a;
}

__device__ __forceinline__ void ldsm_x4(uint32_t* r, uint32_t addr) {
    asm volatile("ldmatrix.sync.aligned.m8n8.x4.shared.b16 {%0,%1,%2,%3}, [%4];"
        : "=r"(r[0]), "=r"(r[1]), "=r"(r[2]), "=r"(r[3]) : "r"(addr));
}

// D(16x8 f32) += A(16x16 bf16) * B(16x8 bf16, col) ; accumulate in place
__device__ __forceinline__ void mma_bf16(float* d, const uint32_t* a, uint32_t b0, uint32_t b1) {
    asm volatile(
        "mma.sync.aligned.m16n8k16.row.col.f32.bf16.bf16.f32 "
        "{%0,%1,%2,%3}, {%4,%5,%6,%7}, {%8,%9}, {%0,%1,%2,%3};"
        : "+f"(d[0]), "+f"(d[1]), "+f"(d[2]), "+f"(d[3])
        : "r"(a[0]), "r"(a[1]), "r"(a[2]), "r"(a[3]), "r"(b0), "r"(b1));
}

__device__ __forceinline__ uint32_t packbf(float lo, float hi) {
    __nv_bfloat162 t = __floats2bfloat162_rn(lo, hi);
    return *reinterpret_cast<uint32_t*>(&t);
}

// ===========================================================================
// bf16x3 split GEMM-NT on mma.sync: C[M,N] = A[M,K]*B[N,K]^T, fp32 in/out.
// 128x128 CTA tile, K-chunk 64, double-buffered SW128 smem.
// Requires M,N % 128 == 0, K % 64 == 0.
// ===========================================================================
#define TILE_B 16384                    // 128 rows x 128 bytes (64 bf16)
#define BUF_B  (4 * TILE_B)             // Ah, Al, Bh, Bl
#define GEMM_SMEM (2 * BUF_B)           // 131072 B

__global__ __launch_bounds__(256) void gemm_mma(
    const float* __restrict__ A, const float* __restrict__ B,
    float* __restrict__ C, int M, int N, int K)
{
    extern __shared__ char smem[];
    const uint32_t sbase = smem_u32(smem);
    const int tid  = threadIdx.x;
    const int wid  = tid >> 5;
    const int lane = tid & 31;
    const int bm = blockIdx.y * 128;
    const int bn = blockIdx.x * 128;

    const int warpM = (wid & 1) * 64;    // 2 warps over M (64 each)
    const int warpN = (wid >> 1) * 32;   // 4 warps over N (32 each)

    // ldmatrix lane geometry (row within 16-row group, k-halfword group)
    const int lrow = lane & 15;
    const int kb   = (lane >> 4) * 16;   // byte offset of the 8-elem k group

    // A-tile ldmatrix bases (4 m16 tiles), swizzle term from row low bits
    uint32_t aRow[4], aSwz[4];
#pragma unroll
    for (int mi = 0; mi < 4; mi++) {
        int r = warpM + mi * 16 + lrow;
        aRow[mi] = (uint32_t)(r * 128);
        aSwz[mi] = (uint32_t)((r & 7) << 4);
    }
    // B-tile ldmatrix bases (2 n16 groups)
    uint32_t bRow[2], bSwz[2];
#pragma unroll
    for (int nj = 0; nj < 2; nj++) {
        int r = warpN + nj * 16 + lrow;
        bRow[nj] = (uint32_t)(r * 128);
        bSwz[nj] = (uint32_t)((r & 7) << 4);
    }

    // global staging geometry: each thread owns one row-half (32 fp32) of A and B
    const int row     = tid >> 1;
    const int colbase = (tid & 1) << 5;
    const float* Ap = A + (size_t)(bm + row) * K + colbase;
    const float* Bp = B + (size_t)(bn + row) * K + colbase;
    // swizzled store offsets (row*128 + 16B-chunk), chunk = (colbase+g*8)*2
    uint32_t stO[4];
#pragma unroll
    for (int g = 0; g < 4; g++) {
        uint32_t off = (uint32_t)(row * 128 + (colbase + g * 8) * 2);
        stO[g] = off ^ ((off >> 3) & 0x70);
    }

    float acc[4][4][4];
#pragma unroll
    for (int mi = 0; mi < 4; mi++)
#pragma unroll
        for (int nj = 0; nj < 4; nj++)
#pragma unroll
            for (int k = 0; k < 4; k++) acc[mi][nj][k] = 0.f;

    const int nch = K >> 6;
    float4 ra[2], rb[2];   // staged gmem data for current chunk

    // prologue: fetch chunk 0
    ra[0] = *(const float4*)(Ap + 0); ra[1] = *(const float4*)(Ap + 4);
    rb[0] = *(const float4*)(Bp + 0); rb[1] = *(const float4*)(Bp + 4);

    for (int ch = 0; ch < nch; ch++) {
        const uint32_t bufb = sbase + (uint32_t)(ch & 1) * BUF_B;
        char* bufp = smem + (ch & 1) * BUF_B;

        // convert + STS current chunk (g=0 uses prefetched regs)
#pragma unroll
        for (int g = 0; g < 4; g++) {
            float4 a0, a1, b0, b1;
            if (g == 0) { a0 = ra[0]; a1 = ra[1]; b0 = rb[0]; b1 = rb[1]; }
            else {
                a0 = *(const float4*)(Ap + ch * 64 + g * 8);
                a1 = *(const float4*)(Ap + ch * 64 + g * 8 + 4);
                b0 = *(const float4*)(Bp + ch * 64 + g * 8);
                b1 = *(const float4*)(Bp + ch * 64 + g * 8 + 4);
            }
            {
                float h0 = __bfloat162float(__float2bfloat16_rn(a0.x));
                float h1 = __bfloat162float(__float2bfloat16_rn(a0.y));
                float h2 = __bfloat162float(__float2bfloat16_rn(a0.z));
                float h3 = __bfloat162float(__float2bfloat16_rn(a0.w));
                float h4 = __bfloat162float(__float2bfloat16_rn(a1.x));
                float h5 = __bfloat162float(__float2bfloat16_rn(a1.y));
                float h6 = __bfloat162float(__float2bfloat16_rn(a1.z));
                float h7 = __bfloat162float(__float2bfloat16_rn(a1.w));
                *(uint4*)(bufp + 0 * TILE_B + stO[g]) =
                    make_uint4(packbf(h0,h1), packbf(h2,h3), packbf(h4,h5), packbf(h6,h7));
                *(uint4*)(bufp + 1 * TILE_B + stO[g]) =
                    make_uint4(packbf(a0.x-h0, a0.y-h1), packbf(a0.z-h2, a0.w-h3),
                               packbf(a1.x-h4, a1.y-h5), packbf(a1.z-h6, a1.w-h7));
            }
            {
                float h0 = __bfloat162float(__float2bfloat16_rn(b0.x));
                float h1 = __bfloat162float(__float2bfloat16_rn(b0.y));
                float h2 = __bfloat162float(__float2bfloat16_rn(b0.z));
                float h3 = __bfloat162float(__float2bfloat16_rn(b0.w));
                float h4 = __bfloat162float(__float2bfloat16_rn(b1.x));
                float h5 = __bfloat162float(__float2bfloat16_rn(b1.y));
                float h6 = __bfloat162float(__float2bfloat16_rn(b1.z));
                float h7 = __bfloat162float(__float2bfloat16_rn(b1.w));
                *(uint4*)(bufp + 2 * TILE_B + stO[g]) =
                    make_uint4(packbf(h0,h1), packbf(h2,h3), packbf(h4,h5), packbf(h6,h7));
                *(uint4*)(bufp + 3 * TILE_B + stO[g]) =
                    make_uint4(packbf(b0.x-h0, b0.y-h1), packbf(b0.z-h2, b0.w-h3),
                               packbf(b1.x-h4, b1.y-h5), packbf(b1.z-h6, b1.w-h7));
            }
        }
        __syncthreads();

        // prefetch next chunk into regs (hides gmem latency under MMAs)
        if (ch + 1 < nch) {
            ra[0] = *(const float4*)(Ap + (ch+1) * 64);
            ra[1] = *(const float4*)(Ap + (ch+1) * 64 + 4);
            rb[0] = *(const float4*)(Bp + (ch+1) * 64);
            rb[1] = *(const float4*)(Bp + (ch+1) * 64 + 4);
        }

        // MMA over 4 k16 steps, 3 split terms
#pragma unroll
        for (int ks = 0; ks < 4; ks++) {
            const uint32_t koff = (uint32_t)(ks * 32 + kb);
            uint32_t ah[4][4], al[4][4], bh[2][4], bl[2][4];
#pragma unroll
            for (int mi = 0; mi < 4; mi++)
                ldsm_x4(ah[mi], bufb + 0*TILE_B + aRow[mi] + (koff ^ aSwz[mi]));
#pragma unroll
            for (int nj = 0; nj < 2; nj++)
                ldsm_x4(bh[nj], bufb + 2*TILE_B + bRow[nj] + (koff ^ bSwz[nj]));
#pragma unroll
            for (int mi = 0; mi < 4; mi++)
#pragma unroll
                for (int nj = 0; nj < 4; nj++)
                    mma_bf16(acc[mi][nj], ah[mi], bh[nj>>1][nj&1], bh[nj>>1][(nj&1)+2]);
#pragma unroll
            for (int nj = 0; nj < 2; nj++)
                ldsm_x4(bl[nj], bufb + 3*TILE_B + bRow[nj] + (koff ^ bSwz[nj]));
#pragma unroll
            for (int mi = 0; mi < 4; mi++)
#pragma unroll
                for (int nj = 0; nj < 4; nj++)
                    mma_bf16(acc[mi][nj], ah[mi], bl[nj>>1][nj&1], bl[nj>>1][(nj&1)+2]);
#pragma unroll
            for (int mi = 0; mi < 4; mi++)
                ldsm_x4(al[mi], bufb + 1*TILE_B + aRow[mi] + (koff ^ aSwz[mi]));
#pragma unroll
            for (int mi = 0; mi < 4; mi++)
#pragma unroll
                for (int nj = 0; nj < 4; nj++)
                    mma_bf16(acc[mi][nj], al[mi], bh[nj>>1][nj&1], bh[nj>>1][(nj&1)+2]);
        }
        __syncthreads();
    }

    // epilogue: frag (mi,nj): rows +lane>>2 and +8, cols nj*8 + (lane&3)*2
    const int er = lane >> 2;
    const int ec = (lane & 3) * 2;
#pragma unroll
    for (int mi = 0; mi < 4; mi++) {
        const int r0 = bm + warpM + mi * 16 + er;
#pragma unroll
        for (int nj = 0; nj < 4; nj++) {
            const int c = bn + warpN + nj * 8 + ec;
            *(float2*)&C[(size_t)r0 * N + c]       = make_float2(acc[mi][nj][0], acc[mi][nj][1]);
            *(float2*)&C[(size_t)(r0 + 8) * N + c] = make_float2(acc[mi][nj][2], acc[mi][nj][3]);
        }
    }
}

// ===========================================================================
// Flash attention (fp32, online softmax) — unchanged from passing R1 kernel
// ===========================================================================
__device__ __forceinline__ int swz_el(int row, int col) {
    return row * 64 + ((((col >> 2) ^ ((row >> 2) & 7)) << 2) | (col & 3));
}

__global__ __launch_bounds__(256) void flash_attn_kernel(
    const float* __restrict__ qkv,     // [B,N,3,H,HD]
    const float* __restrict__ head_w,  // [H]
    float* __restrict__ ao)            // [B,N,C]
{
    __shared__ float Qt [64 * 64];
    __shared__ float KPs[64 * 64];
    __shared__ float Vs [64 * 64];

    const int tid = threadIdx.x;
    const int tx = tid & 15;
    const int ty = tid >> 4;
    const int q0 = blockIdx.x * 64;
    const int h  = blockIdx.y;
    const int b  = blockIdx.z;

    float hw;
    {
        float mx = -1e30f;
#pragma unroll
        for (int i = 0; i < NHEAD; i++) mx = fmaxf(mx, head_w[i]);
        float ssum = 0.f;
#pragma unroll
        for (int i = 0; i < NHEAD; i++) ssum += __expf(head_w[i] - mx);
        hw = __expf(head_w[h] - mx) / ssum;
    }

    {
        const float* qbase = qkv + (size_t)(b * SEQ + q0) * 3 * DIMC + h * HD;
#pragma unroll
        for (int it = 0; it < 4; it++) {
            int i  = tid + it * 256;
            int r  = i >> 4;
            int c4 = (i & 15) << 2;
            float4 v = *(const float4*)(qbase + (size_t)r * 3 * DIMC + c4);
            Qt[swz_el(c4 + 0, r)] = v.x;
            Qt[swz_el(c4 + 1, r)] = v.y;
            Qt[swz_el(c4 + 2, r)] = v.z;
            Qt[swz_el(c4 + 3, r)] = v.w;
        }
    }

    float o[4][4];
    float m_r[4], l_r[4];
#pragma unroll
    for (int i = 0; i < 4; i++) {
        m_r[i] = -1e30f; l_r[i] = 0.f;
#pragma unroll
        for (int j = 0; j < 4; j++) o[i][j] = 0.f;
    }

    for (int t0 = 0; t0 < SEQ; t0 += 64) {
        __syncthreads();
        {
            const float* kbase = qkv + ((size_t)(b * SEQ + t0) * 3 + 1) * DIMC + h * HD;
            const float* vbase = qkv + ((size_t)(b * SEQ + t0) * 3 + 2) * DIMC + h * HD;
#pragma unroll
            for (int it = 0; it < 4; it++) {
                int i  = tid + it * 256;
                int r  = i >> 4;
                int c4 = (i & 15) << 2;
                float4 kv = *(const float4*)(kbase + (size_t)r * 3 * DIMC + c4);
                KPs[swz_el(c4 + 0, r)] = kv.x;
                KPs[swz_el(c4 + 1, r)] = kv.y;
                KPs[swz_el(c4 + 2, r)] = kv.z;
                KPs[swz_el(c4 + 3, r)] = kv.w;
                float4 vv = *(const float4*)(vbase + (size_t)r * 3 * DIMC + c4);
                *(float4*)&Vs[r * 64 + c4] = vv;
            }
        }
        __syncthreads();

        float s[4][4];
#pragma unroll
        for (int i = 0; i < 4; i++)
#pragma unroll
            for (int j = 0; j < 4; j++) s[i][j] = 0.f;

#pragma unroll 8
        for (int d = 0; d < HD; d++) {
            int sw = (d >> 2) & 7;
            float4 qv = *(const float4*)&Qt [d * 64 + ((ty ^ sw) << 2)];
            float4 kv = *(const float4*)&KPs[d * 64 + ((tx ^ sw) << 2)];
            s[0][0] += qv.x * kv.x; s[0][1] += qv.x * kv.y; s[0][2] += qv.x * kv.z; s[0][3] += qv.x * kv.w;
            s[1][0] += qv.y * kv.x; s[1][1] += qv.y * kv.y; s[1][2] += qv.y * kv.z; s[1][3] += qv.y * kv.w;
            s[2][0] += qv.z * kv.x; s[2][1] += qv.z * kv.y; s[2][2] += qv.z * kv.z; s[2][3] += qv.z * kv.w;
            s[3][0] += qv.w * kv.x; s[3][1] += qv.w * kv.y; s[3][2] += qv.w * kv.z; s[3][3] += qv.w * kv.w;
        }

#pragma unroll
        for (int i = 0; i < 4; i++) {
#pragma unroll
            for (int j = 0; j < 4; j++) s[i][j] *= SCALE;
            float rm = fmaxf(fmaxf(s[i][0], s[i][1]), fmaxf(s[i][2], s[i][3]));
#pragma unroll
            for (int off = 8; off > 0; off >>= 1)
                rm = fmaxf(rm, __shfl_xor_sync(0xffffffffu, rm, off));
            float mn = fmaxf(m_r[i], rm);
            float alpha = __expf(m_r[i] - mn);
            m_r[i] = mn;
            float rs = 0.f;
#pragma unroll
            for (int j = 0; j < 4; j++) { s[i][j] = __expf(s[i][j] - mn); rs += s[i][j]; }
#pragma unroll
            for (int off = 8; off > 0; off >>= 1)
                rs += __shfl_xor_sync(0xffffffffu, rs, off);
            l_r[i] = l_r[i] * alpha + rs;
#pragma unroll
            for (int j = 0; j < 4; j++) o[i][j] *= alpha;
        }

        __syncthreads();
#pragma unroll
        for (int i = 0; i < 4; i++) {
            int r = 4 * ty + i;
            float4 pv = make_float4(s[i][0], s[i][1], s[i][2], s[i][3]);
            *(float4*)&KPs[r * 64 + ((tx ^ ((r >> 2) & 7)) << 2)] = pv;
        }
        __syncthreads();

#pragma unroll 2
        for (int k4 = 0; k4 < 16; k4++) {
            float4 vv0 = *(const float4*)&Vs[(4 * k4 + 0) * 64 + 4 * tx];
            float4 vv1 = *(const float4*)&Vs[(4 * k4 + 1) * 64 + 4 * tx];
            float4 vv2 = *(const float4*)&Vs[(4 * k4 + 2) * 64 + 4 * tx];
            float4 vv3 = *(const float4*)&Vs[(4 * k4 + 3) * 64 + 4 * tx];
#pragma unroll
            for (int i = 0; i < 4; i++) {
                int r = 4 * ty + i;
                float4 prv = *(const float4*)&KPs[r * 64 + ((k4 ^ ((r >> 2) & 7)) << 2)];
                o[i][0] += prv.x * vv0.x; o[i][1] += prv.x * vv0.y; o[i][2] += prv.x * vv0.z; o[i][3] += prv.x * vv0.w;
                o[i][0] += prv.y * vv1.x; o[i][1] += prv.y * vv1.y; o[i][2] += prv.y * vv1.z; o[i][3] += prv.y * vv1.w;
                o[i][0] += prv.z * vv2.x; o[i][1] += prv.z * vv2.y; o[i][2] += prv.z * vv2.z; o[i][3] += prv.z * vv2.w;
                o[i][0] += prv.w * vv3.x; o[i][1] += prv.w * vv3.y; o[i][2] += prv.w * vv3.z; o[i][3] += prv.w * vv3.w;
            }
        }
    }

#pragma unroll
    for (int i = 0; i < 4; i++) {
        float inv = hw / l_r[i];
        int r = q0 + 4 * ty + i;
        float4 ov = make_float4(o[i][0] * inv, o[i][1] * inv, o[i][2] * inv, o[i][3] * inv);
        *(float4*)&ao[(size_t)(b * SEQ + r) * DIMC + h * HD + 4 * tx] = ov;
    }
}

// ===========================================================================
extern "C" void kernel_launch(void* const* d_in, const int* in_sizes, int n_in,
                              void* d_out, int out_size)
{
    const float* x      = (const float*)d_in[0];
    const float* w_qkv  = (const float*)d_in[1];
    const float* w_proj = (const float*)d_in[2];
    const float* head_w = (const float*)d_in[3];
    float* out = (float*)d_out;

    float *qkv_ptr, *ao_ptr;
    cudaGetSymbolAddress((void**)&qkv_ptr, g_qkv);
    cudaGetSymbolAddress((void**)&ao_ptr,  g_ao);

    static bool attr_set = false;
    if (!attr_set) {
        cudaFuncSetAttribute(gemm_mma, cudaFuncAttributeMaxDynamicSharedMemorySize, GEMM_SMEM);
        attr_set = true;
    }

    // 1) QKV projection: [4096,1024] x [3072,1024]^T -> [4096,3072]
    dim3 g1(QKV_N / 128, M_TOT / 128);
    gemm_mma<<<g1, 256, GEMM_SMEM>>>(x, w_qkv, qkv_ptr, M_TOT, QKV_N, DIMC);

    // 2) flash attention + head-weight scale -> g_ao
    dim3 g2(SEQ / 64, NHEAD, BATCH);
    flash_attn_kernel<<<g2, 256>>>(qkv_ptr, head_w, ao_ptr);

    // 3) output projection: [4096,1024] x [1024,1024]^T -> out
    dim3 g3(DIMC / 128, M_TOT / 128);
    gemm_mma<<<g3, 256, GEMM_SMEM>>>(ao_ptr, w_proj, out, M_TOT, DIMC, DIMC);
}

// round 5
// speedup vs baseline: 1.6493x; 1.3746x over previous
#include <cuda_runtime.h>
#include <cuda_bf16.h>
#include <cstdint>

#define BATCH 2
#define SEQ   2048
#define DIMC  1024
#define NHEAD 16
#define HD    64
#define SCALE 0.125f            // 64^-0.5

#define M_TOT (BATCH*SEQ)       // 4096
#define QKV_N (3*DIMC)          // 3072

// Scratch (allocation-free rule: __device__ globals)
__device__ float g_qkv[(size_t)M_TOT * QKV_N];   // [B,N,3,H,HD]
__device__ float g_ao [(size_t)M_TOT * DIMC];    // attention out [B,N,C]

// ===========================================================================
// Base-target (sm_103) tensor-core primitives: ldmatrix + mma.sync
// ===========================================================================
__device__ __forceinline__ uint32_t smem_u32(const void* p) {
    uint32_t a;
    asm("{ .reg .u64 t; cvta.to.shared.u64 t, %1; cvt.u32.u64 %0, t; }" : "=r"(a) : "l"(p));
    return a;
}

__device__ __forceinline__ void ldsm_x4(uint32_t* r, uint32_t addr) {
    asm volatile("ldmatrix.sync.aligned.m8n8.x4.shared.b16 {%0,%1,%2,%3}, [%4];"
        : "=r"(r[0]), "=r"(r[1]), "=r"(r[2]), "=r"(r[3]) : "r"(addr));
}
__device__ __forceinline__ void ldsm_x4_t(uint32_t* r, uint32_t addr) {
    asm volatile("ldmatrix.sync.aligned.m8n8.x4.trans.shared.b16 {%0,%1,%2,%3}, [%4];"
        : "=r"(r[0]), "=r"(r[1]), "=r"(r[2]), "=r"(r[3]) : "r"(addr));
}

// D(16x8 f32) += A(16x16 bf16) * B(16x8 bf16, col) ; accumulate in place
__device__ __forceinline__ void mma_bf16(float* d, const uint32_t* a, uint32_t b0, uint32_t b1) {
    asm volatile(
        "mma.sync.aligned.m16n8k16.row.col.f32.bf16.bf16.f32 "
        "{%0,%1,%2,%3}, {%4,%5,%6,%7}, {%8,%9}, {%0,%1,%2,%3};"
        : "+f"(d[0]), "+f"(d[1]), "+f"(d[2]), "+f"(d[3])
        : "r"(a[0]), "r"(a[1]), "r"(a[2]), "r"(a[3]), "r"(b0), "r"(b1));
}

__device__ __forceinline__ uint32_t packbf(float lo, float hi) {
    __nv_bfloat162 t = __floats2bfloat162_rn(lo, hi);
    return *reinterpret_cast<uint32_t*>(&t);
}

// ===========================================================================
// bf16x3 split GEMM-NT on mma.sync (unchanged from R4 passing kernel)
// ===========================================================================
#define TILE_B 16384
#define BUF_B  (4 * TILE_B)
#define GEMM_SMEM (2 * BUF_B)

__global__ __launch_bounds__(256) void gemm_mma(
    const float* __restrict__ A, const float* __restrict__ B,
    float* __restrict__ C, int M, int N, int K)
{
    extern __shared__ char smem[];
    const uint32_t sbase = smem_u32(smem);
    const int tid  = threadIdx.x;
    const int wid  = tid >> 5;
    const int lane = tid & 31;
    const int bm = blockIdx.y * 128;
    const int bn = blockIdx.x * 128;

    const int warpM = (wid & 1) * 64;
    const int warpN = (wid >> 1) * 32;

    const int lrow = lane & 15;
    const int kb   = (lane >> 4) * 16;

    uint32_t aRow[4], aSwz[4];
#pragma unroll
    for (int mi = 0; mi < 4; mi++) {
        int r = warpM + mi * 16 + lrow;
        aRow[mi] = (uint32_t)(r * 128);
        aSwz[mi] = (uint32_t)((r & 7) << 4);
    }
    uint32_t bRow[2], bSwz[2];
#pragma unroll
    for (int nj = 0; nj < 2; nj++) {
        int r = warpN + nj * 16 + lrow;
        bRow[nj] = (uint32_t)(r * 128);
        bSwz[nj] = (uint32_t)((r & 7) << 4);
    }

    const int row     = tid >> 1;
    const int colbase = (tid & 1) << 5;
    const float* Ap = A + (size_t)(bm + row) * K + colbase;
    const float* Bp = B + (size_t)(bn + row) * K + colbase;
    uint32_t stO[4];
#pragma unroll
    for (int g = 0; g < 4; g++) {
        uint32_t off = (uint32_t)(row * 128 + (colbase + g * 8) * 2);
        stO[g] = off ^ ((off >> 3) & 0x70);
    }

    float acc[4][4][4];
#pragma unroll
    for (int mi = 0; mi < 4; mi++)
#pragma unroll
        for (int nj = 0; nj < 4; nj++)
#pragma unroll
            for (int k = 0; k < 4; k++) acc[mi][nj][k] = 0.f;

    const int nch = K >> 6;
    float4 ra[2], rb[2];

    ra[0] = *(const float4*)(Ap + 0); ra[1] = *(const float4*)(Ap + 4);
    rb[0] = *(const float4*)(Bp + 0); rb[1] = *(const float4*)(Bp + 4);

    for (int ch = 0; ch < nch; ch++) {
        const uint32_t bufb = sbase + (uint32_t)(ch & 1) * BUF_B;
        char* bufp = smem + (ch & 1) * BUF_B;

#pragma unroll
        for (int g = 0; g < 4; g++) {
            float4 a0, a1, b0, b1;
            if (g == 0) { a0 = ra[0]; a1 = ra[1]; b0 = rb[0]; b1 = rb[1]; }
            else {
                a0 = *(const float4*)(Ap + ch * 64 + g * 8);
                a1 = *(const float4*)(Ap + ch * 64 + g * 8 + 4);
                b0 = *(const float4*)(Bp + ch * 64 + g * 8);
                b1 = *(const float4*)(Bp + ch * 64 + g * 8 + 4);
            }
            {
                float h0 = __bfloat162float(__float2bfloat16_rn(a0.x));
                float h1 = __bfloat162float(__float2bfloat16_rn(a0.y));
                float h2 = __bfloat162float(__float2bfloat16_rn(a0.z));
                float h3 = __bfloat162float(__float2bfloat16_rn(a0.w));
                float h4 = __bfloat162float(__float2bfloat16_rn(a1.x));
                float h5 = __bfloat162float(__float2bfloat16_rn(a1.y));
                float h6 = __bfloat162float(__float2bfloat16_rn(a1.z));
                float h7 = __bfloat162float(__float2bfloat16_rn(a1.w));
                *(uint4*)(bufp + 0 * TILE_B + stO[g]) =
                    make_uint4(packbf(h0,h1), packbf(h2,h3), packbf(h4,h5), packbf(h6,h7));
                *(uint4*)(bufp + 1 * TILE_B + stO[g]) =
                    make_uint4(packbf(a0.x-h0, a0.y-h1), packbf(a0.z-h2, a0.w-h3),
                               packbf(a1.x-h4, a1.y-h5), packbf(a1.z-h6, a1.w-h7));
            }
            {
                float h0 = __bfloat162float(__float2bfloat16_rn(b0.x));
                float h1 = __bfloat162float(__float2bfloat16_rn(b0.y));
                float h2 = __bfloat162float(__float2bfloat16_rn(b0.z));
                float h3 = __bfloat162float(__float2bfloat16_rn(b0.w));
                float h4 = __bfloat162float(__float2bfloat16_rn(b1.x));
                float h5 = __bfloat162float(__float2bfloat16_rn(b1.y));
                float h6 = __bfloat162float(__float2bfloat16_rn(b1.z));
                float h7 = __bfloat162float(__float2bfloat16_rn(b1.w));
                *(uint4*)(bufp + 2 * TILE_B + stO[g]) =
                    make_uint4(packbf(h0,h1), packbf(h2,h3), packbf(h4,h5), packbf(h6,h7));
                *(uint4*)(bufp + 3 * TILE_B + stO[g]) =
                    make_uint4(packbf(b0.x-h0, b0.y-h1), packbf(b0.z-h2, b0.w-h3),
                               packbf(b1.x-h4, b1.y-h5), packbf(b1.z-h6, b1.w-h7));
            }
        }
        __syncthreads();

        if (ch + 1 < nch) {
            ra[0] = *(const float4*)(Ap + (ch+1) * 64);
            ra[1] = *(const float4*)(Ap + (ch+1) * 64 + 4);
            rb[0] = *(const float4*)(Bp + (ch+1) * 64);
            rb[1] = *(const float4*)(Bp + (ch+1) * 64 + 4);
        }

#pragma unroll
        for (int ks = 0; ks < 4; ks++) {
            const uint32_t koff = (uint32_t)(ks * 32 + kb);
            uint32_t ah[4][4], al[4][4], bh[2][4], bl[2][4];
#pragma unroll
            for (int mi = 0; mi < 4; mi++)
                ldsm_x4(ah[mi], bufb + 0*TILE_B + aRow[mi] + (koff ^ aSwz[mi]));
#pragma unroll
            for (int nj = 0; nj < 2; nj++)
                ldsm_x4(bh[nj], bufb + 2*TILE_B + bRow[nj] + (koff ^ bSwz[nj]));
#pragma unroll
            for (int mi = 0; mi < 4; mi++)
#pragma unroll
                for (int nj = 0; nj < 4; nj++)
                    mma_bf16(acc[mi][nj], ah[mi], bh[nj>>1][nj&1], bh[nj>>1][(nj&1)+2]);
#pragma unroll
            for (int nj = 0; nj < 2; nj++)
                ldsm_x4(bl[nj], bufb + 3*TILE_B + bRow[nj] + (koff ^ bSwz[nj]));
#pragma unroll
            for (int mi = 0; mi < 4; mi++)
#pragma unroll
                for (int nj = 0; nj < 4; nj++)
                    mma_bf16(acc[mi][nj], ah[mi], bl[nj>>1][nj&1], bl[nj>>1][(nj&1)+2]);
#pragma unroll
            for (int mi = 0; mi < 4; mi++)
                ldsm_x4(al[mi], bufb + 1*TILE_B + aRow[mi] + (koff ^ aSwz[mi]));
#pragma unroll
            for (int mi = 0; mi < 4; mi++)
#pragma unroll
                for (int nj = 0; nj < 4; nj++)
                    mma_bf16(acc[mi][nj], al[mi], bh[nj>>1][nj&1], bh[nj>>1][(nj&1)+2]);
        }
        __syncthreads();
    }

    const int er = lane >> 2;
    const int ec = (lane & 3) * 2;
#pragma unroll
    for (int mi = 0; mi < 4; mi++) {
        const int r0 = bm + warpM + mi * 16 + er;
#pragma unroll
        for (int nj = 0; nj < 4; nj++) {
            const int c = bn + warpN + nj * 8 + ec;
            *(float2*)&C[(size_t)r0 * N + c]       = make_float2(acc[mi][nj][0], acc[mi][nj][1]);
            *(float2*)&C[(size_t)(r0 + 8) * N + c] = make_float2(acc[mi][nj][2], acc[mi][nj][3]);
        }
    }
}

// ===========================================================================
// Tensor-core flash attention, bf16x3 splits on QK^T and PV.
// BQ=128 (warp = 16 rows), BK=128, HD=64. 256 threads.
// smem: Kh,Kl,Vh,Vl 16KB each (swizzled, 128B rows). Q frags in registers.
// ===========================================================================
#define FA_SMEM (4 * 16384)

__global__ __launch_bounds__(256) void flash_mma(
    const float* __restrict__ qkv,     // [B,N,3,H,HD]
    const float* __restrict__ head_w,  // [H]
    float* __restrict__ ao)            // [B,N,C]
{
    extern __shared__ char smem[];
    const uint32_t sb = smem_u32(smem);
    const uint32_t sKH = sb, sKL = sb + 16384, sVH = sb + 32768, sVL = sb + 49152;
    char *pKH = smem, *pKL = smem + 16384, *pVH = smem + 32768, *pVL = smem + 49152;

    const int tid  = threadIdx.x;
    const int wid  = tid >> 5;
    const int lane = tid & 31;
    const int q0 = blockIdx.x * 128;
    const int h  = blockIdx.y;
    const int b  = blockIdx.z;

    // head-weight softmax
    float hw;
    {
        float mx = -1e30f;
#pragma unroll
        for (int i = 0; i < NHEAD; i++) mx = fmaxf(mx, head_w[i]);
        float ssum = 0.f;
#pragma unroll
        for (int i = 0; i < NHEAD; i++) ssum += __expf(head_w[i] - mx);
        hw = __expf(head_w[h] - mx) / ssum;
    }

    // staging geometry (same as gemm): thread owns row=tid>>1, 32-col half
    const int row     = tid >> 1;
    const int colbase = (tid & 1) << 5;
    uint32_t stO[4];
#pragma unroll
    for (int g = 0; g < 4; g++) {
        uint32_t off = (uint32_t)(row * 128 + (colbase + g * 8) * 2);
        stO[g] = off ^ ((off >> 3) & 0x70);
    }

    // ---- stage Q (hi->KH, lo->KL), then load Q fragments to registers ----
    {
        const float* qp = qkv + (size_t)(b * SEQ + q0 + row) * 3 * DIMC + h * HD + colbase;
#pragma unroll
        for (int g = 0; g < 2; g++) {   // 32 floats = 2 groups of 16
            float4 a0 = *(const float4*)(qp + g * 16);
            float4 a1 = *(const float4*)(qp + g * 16 + 4);
            float4 a2 = *(const float4*)(qp + g * 16 + 8);
            float4 a3 = *(const float4*)(qp + g * 16 + 12);
            float h0 = __bfloat162float(__float2bfloat16_rn(a0.x));
            float h1 = __bfloat162float(__float2bfloat16_rn(a0.y));
            float h2 = __bfloat162float(__float2bfloat16_rn(a0.z));
            float h3 = __bfloat162float(__float2bfloat16_rn(a0.w));
            float h4 = __bfloat162float(__float2bfloat16_rn(a1.x));
            float h5 = __bfloat162float(__float2bfloat16_rn(a1.y));
            float h6 = __bfloat162float(__float2bfloat16_rn(a1.z));
            float h7 = __bfloat162float(__float2bfloat16_rn(a1.w));
            *(uint4*)(pKH + stO[2*g]) = make_uint4(packbf(h0,h1), packbf(h2,h3), packbf(h4,h5), packbf(h6,h7));
            *(uint4*)(pKL + stO[2*g]) = make_uint4(packbf(a0.x-h0,a0.y-h1), packbf(a0.z-h2,a0.w-h3),
                                                   packbf(a1.x-h4,a1.y-h5), packbf(a1.z-h6,a1.w-h7));
            h0 = __bfloat162float(__float2bfloat16_rn(a2.x));
            h1 = __bfloat162float(__float2bfloat16_rn(a2.y));
            h2 = __bfloat162float(__float2bfloat16_rn(a2.z));
            h3 = __bfloat162float(__float2bfloat16_rn(a2.w));
            h4 = __bfloat162float(__float2bfloat16_rn(a3.x));
            h5 = __bfloat162float(__float2bfloat16_rn(a3.y));
            h6 = __bfloat162float(__float2bfloat16_rn(a3.z));
            h7 = __bfloat162float(__float2bfloat16_rn(a3.w));
            *(uint4*)(pKH + stO[2*g+1]) = make_uint4(packbf(h0,h1), packbf(h2,h3), packbf(h4,h5), packbf(h6,h7));
            *(uint4*)(pKL + stO[2*g+1]) = make_uint4(packbf(a2.x-h0,a2.y-h1), packbf(a2.z-h2,a2.w-h3),
                                                     packbf(a3.x-h4,a3.y-h5), packbf(a3.z-h6,a3.w-h7));
        }
    }
    __syncthreads();

    const int lrow = lane & 15;
    const int kb   = (lane >> 4) * 16;
    const uint32_t aOff = (uint32_t)((wid * 16 + lrow) * 128);
    const uint32_t aSwz = (uint32_t)((lrow & 7) << 4);

    uint32_t qh[4][4], ql[4][4];
#pragma unroll
    for (int ks = 0; ks < 4; ks++) {
        const uint32_t koff = (uint32_t)(ks * 32 + kb);
        ldsm_x4(qh[ks], sKH + aOff + (koff ^ aSwz));
        ldsm_x4(ql[ks], sKL + aOff + (koff ^ aSwz));
    }

    // K-frag ldmatrix bases (8 n16 groups over 128 keys)
    uint32_t bOff[8];
#pragma unroll
    for (int g = 0; g < 8; g++) bOff[g] = (uint32_t)((g * 16 + lrow) * 128);
    const uint32_t bSwz = (uint32_t)((lrow & 7) << 4);
    // V trans-ldmatrix lane geometry
    const uint32_t vRowBase = (uint32_t)(lane & 15);
    const uint32_t vColPart = (uint32_t)((lane >> 4) * 16);

    float m_r[2] = {-1e30f, -1e30f};
    float l_r[2] = {0.f, 0.f};
    float o[8][4];
#pragma unroll
    for (int g = 0; g < 8; g++)
#pragma unroll
        for (int e = 0; e < 4; e++) o[g][e] = 0.f;

    for (int kt = 0; kt < SEQ / 128; kt++) {
        __syncthreads();   // previous iteration's readers done
        // ---- load K,V tile, split, store ----
        {
            const float* kp = qkv + ((size_t)(b * SEQ + kt * 128 + row) * 3 + 1) * DIMC + h * HD + colbase;
            const float* vp = qkv + ((size_t)(b * SEQ + kt * 128 + row) * 3 + 2) * DIMC + h * HD + colbase;
#pragma unroll
            for (int g = 0; g < 4; g++) {
                float4 a0 = *(const float4*)(kp + g * 8);
                float4 a1 = *(const float4*)(kp + g * 8 + 4);
                float h0 = __bfloat162float(__float2bfloat16_rn(a0.x));
                float h1 = __bfloat162float(__float2bfloat16_rn(a0.y));
                float h2 = __bfloat162float(__float2bfloat16_rn(a0.z));
                float h3 = __bfloat162float(__float2bfloat16_rn(a0.w));
                float h4 = __bfloat162float(__float2bfloat16_rn(a1.x));
                float h5 = __bfloat162float(__float2bfloat16_rn(a1.y));
                float h6 = __bfloat162float(__float2bfloat16_rn(a1.z));
                float h7 = __bfloat162float(__float2bfloat16_rn(a1.w));
                *(uint4*)(pKH + stO[g]) = make_uint4(packbf(h0,h1), packbf(h2,h3), packbf(h4,h5), packbf(h6,h7));
                *(uint4*)(pKL + stO[g]) = make_uint4(packbf(a0.x-h0,a0.y-h1), packbf(a0.z-h2,a0.w-h3),
                                                     packbf(a1.x-h4,a1.y-h5), packbf(a1.z-h6,a1.w-h7));
                float4 b0 = *(const float4*)(vp + g * 8);
                float4 b1 = *(const float4*)(vp + g * 8 + 4);
                h0 = __bfloat162float(__float2bfloat16_rn(b0.x));
                h1 = __bfloat162float(__float2bfloat16_rn(b0.y));
                h2 = __bfloat162float(__float2bfloat16_rn(b0.z));
                h3 = __bfloat162float(__float2bfloat16_rn(b0.w));
                h4 = __bfloat162float(__float2bfloat16_rn(b1.x));
                h5 = __bfloat162float(__float2bfloat16_rn(b1.y));
                h6 = __bfloat162float(__float2bfloat16_rn(b1.z));
                h7 = __bfloat162float(__float2bfloat16_rn(b1.w));
                *(uint4*)(pVH + stO[g]) = make_uint4(packbf(h0,h1), packbf(h2,h3), packbf(h4,h5), packbf(h6,h7));
                *(uint4*)(pVL + stO[g]) = make_uint4(packbf(b0.x-h0,b0.y-h1), packbf(b0.z-h2,b0.w-h3),
                                                     packbf(b1.x-h4,b1.y-h5), packbf(b1.z-h6,b1.w-h7));
            }
        }
        __syncthreads();

        // ---- S = Q K^T (bf16x3), per warp: 16 rows x 128 keys ----
        float s[16][4];
#pragma unroll
        for (int nj = 0; nj < 16; nj++)
#pragma unroll
            for (int e = 0; e < 4; e++) s[nj][e] = 0.f;

#pragma unroll
        for (int ks = 0; ks < 4; ks++) {
            const uint32_t koff = (uint32_t)(ks * 32 + kb);
#pragma unroll
            for (int g = 0; g < 8; g++) {
                uint32_t kh4[4], kl4[4];
                ldsm_x4(kh4, sKH + bOff[g] + (koff ^ bSwz));
                ldsm_x4(kl4, sKL + bOff[g] + (koff ^ bSwz));
                mma_bf16(s[2*g],   qh[ks], kh4[0], kh4[2]);
                mma_bf16(s[2*g+1], qh[ks], kh4[1], kh4[3]);
                mma_bf16(s[2*g],   qh[ks], kl4[0], kl4[2]);
                mma_bf16(s[2*g+1], qh[ks], kl4[1], kl4[3]);
                mma_bf16(s[2*g],   ql[ks], kh4[0], kh4[2]);
                mma_bf16(s[2*g+1], ql[ks], kh4[1], kh4[3]);
            }
        }

        // ---- online softmax (2 rows/thread; quad = lanes sharing lane>>2) ----
        float mx0 = -1e30f, mx1 = -1e30f;
#pragma unroll
        for (int nj = 0; nj < 16; nj++) {
            s[nj][0] *= SCALE; s[nj][1] *= SCALE; s[nj][2] *= SCALE; s[nj][3] *= SCALE;
            mx0 = fmaxf(mx0, fmaxf(s[nj][0], s[nj][1]));
            mx1 = fmaxf(mx1, fmaxf(s[nj][2], s[nj][3]));
        }
        mx0 = fmaxf(mx0, __shfl_xor_sync(0xffffffffu, mx0, 1));
        mx0 = fmaxf(mx0, __shfl_xor_sync(0xffffffffu, mx0, 2));
        mx1 = fmaxf(mx1, __shfl_xor_sync(0xffffffffu, mx1, 1));
        mx1 = fmaxf(mx1, __shfl_xor_sync(0xffffffffu, mx1, 2));
        const float mn0 = fmaxf(m_r[0], mx0);
        const float mn1 = fmaxf(m_r[1], mx1);
        const float alpha0 = __expf(m_r[0] - mn0);
        const float alpha1 = __expf(m_r[1] - mn1);
        m_r[0] = mn0; m_r[1] = mn1;
        float sum0 = 0.f, sum1 = 0.f;
#pragma unroll
        for (int nj = 0; nj < 16; nj++) {
            s[nj][0] = __expf(s[nj][0] - mn0); sum0 += s[nj][0];
            s[nj][1] = __expf(s[nj][1] - mn0); sum0 += s[nj][1];
            s[nj][2] = __expf(s[nj][2] - mn1); sum1 += s[nj][2];
            s[nj][3] = __expf(s[nj][3] - mn1); sum1 += s[nj][3];
        }
        sum0 += __shfl_xor_sync(0xffffffffu, sum0, 1);
        sum0 += __shfl_xor_sync(0xffffffffu, sum0, 2);
        sum1 += __shfl_xor_sync(0xffffffffu, sum1, 1);
        sum1 += __shfl_xor_sync(0xffffffffu, sum1, 2);
        l_r[0] = l_r[0] * alpha0 + sum0;
        l_r[1] = l_r[1] * alpha1 + sum1;
#pragma unroll
        for (int g = 0; g < 8; g++) {
            o[g][0] *= alpha0; o[g][1] *= alpha0;
            o[g][2] *= alpha1; o[g][3] *= alpha1;
        }

        // ---- O += P V (bf16x3), 8 k-steps of 16 keys ----
#pragma unroll
        for (int t = 0; t < 8; t++) {
            // P fragments (hi & lo) from s[2t], s[2t+1]
            uint32_t pa_h[4], pa_l[4];
            {
                float e0 = s[2*t][0], e1 = s[2*t][1], e2 = s[2*t][2], e3 = s[2*t][3];
                float f0 = s[2*t+1][0], f1 = s[2*t+1][1], f2 = s[2*t+1][2], f3 = s[2*t+1][3];
                float h0 = __bfloat162float(__float2bfloat16_rn(e0));
                float h1 = __bfloat162float(__float2bfloat16_rn(e1));
                float h2 = __bfloat162float(__float2bfloat16_rn(e2));
                float h3 = __bfloat162float(__float2bfloat16_rn(e3));
                float g0 = __bfloat162float(__float2bfloat16_rn(f0));
                float g1 = __bfloat162float(__float2bfloat16_rn(f1));
                float g2 = __bfloat162float(__float2bfloat16_rn(f2));
                float g3 = __bfloat162float(__float2bfloat16_rn(f3));
                pa_h[0] = packbf(h0, h1); pa_h[1] = packbf(h2, h3);
                pa_h[2] = packbf(g0, g1); pa_h[3] = packbf(g2, g3);
                pa_l[0] = packbf(e0-h0, e1-h1); pa_l[1] = packbf(e2-h2, e3-h3);
                pa_l[2] = packbf(f0-g0, f1-g1); pa_l[3] = packbf(f2-g2, f3-g3);
            }
#pragma unroll
            for (int g = 0; g < 4; g++) {
                const uint32_t vr = (uint32_t)(16 * t) + vRowBase;
                const uint32_t vc = (uint32_t)(g * 32) + vColPart;
                const uint32_t voff = vr * 128 + (vc ^ ((vr & 7) << 4));
                uint32_t vh4[4], vl4[4];
                ldsm_x4_t(vh4, sVH + voff);
                ldsm_x4_t(vl4, sVL + voff);
                mma_bf16(o[2*g],   pa_h, vh4[0], vh4[1]);
                mma_bf16(o[2*g+1], pa_h, vh4[2], vh4[3]);
                mma_bf16(o[2*g],   pa_h, vl4[0], vl4[1]);
                mma_bf16(o[2*g+1], pa_h, vl4[2], vl4[3]);
                mma_bf16(o[2*g],   pa_l, vh4[0], vh4[1]);
                mma_bf16(o[2*g+1], pa_l, vh4[2], vh4[3]);
            }
        }
    }

    // ---- epilogue: O/l * hw -> ao[b, q, h*64 + d] ----
    const int er = lane >> 2;
    const int ec = (lane & 3) * 2;
    const float inv0 = hw / l_r[0];
    const float inv1 = hw / l_r[1];
    const int r0 = q0 + wid * 16 + er;
#pragma unroll
    for (int g = 0; g < 8; g++) {
        const int d = h * HD + g * 8 + ec;
        *(float2*)&ao[(size_t)(b * SEQ + r0) * DIMC + d] =
            make_float2(o[g][0] * inv0, o[g][1] * inv0);
        *(float2*)&ao[(size_t)(b * SEQ + r0 + 8) * DIMC + d] =
            make_float2(o[g][2] * inv1, o[g][3] * inv1);
    }
}

// ===========================================================================
extern "C" void kernel_launch(void* const* d_in, const int* in_sizes, int n_in,
                              void* d_out, int out_size)
{
    const float* x      = (const float*)d_in[0];
    const float* w_qkv  = (const float*)d_in[1];
    const float* w_proj = (const float*)d_in[2];
    const float* head_w = (const float*)d_in[3];
    float* out = (float*)d_out;

    float *qkv_ptr, *ao_ptr;
    cudaGetSymbolAddress((void**)&qkv_ptr, g_qkv);
    cudaGetSymbolAddress((void**)&ao_ptr,  g_ao);

    cudaFuncSetAttribute(gemm_mma, cudaFuncAttributeMaxDynamicSharedMemorySize, GEMM_SMEM);
    cudaFuncSetAttribute(flash_mma, cudaFuncAttributeMaxDynamicSharedMemorySize, FA_SMEM);

    // 1) QKV projection
    dim3 g1(QKV_N / 128, M_TOT / 128);
    gemm_mma<<<g1, 256, GEMM_SMEM>>>(x, w_qkv, qkv_ptr, M_TOT, QKV_N, DIMC);

    // 2) tensor-core flash attention + head-weight scale
    dim3 g2(SEQ / 128, NHEAD, BATCH);
    flash_mma<<<g2, 256, FA_SMEM>>>(qkv_ptr, head_w, ao_ptr);

    // 3) output projection
    dim3 g3(DIMC / 128, M_TOT / 128);
    gemm_mma<<<g3, 256, GEMM_SMEM>>>(ao_ptr, w_proj, out, M_TOT, DIMC, DIMC);
}

// round 7
// speedup vs baseline: 2.1618x; 1.3108x over previous
#include <cuda_runtime.h>
#include <cuda_bf16.h>
#include <cstdint>

#define BATCH 2
#define SEQ   2048
#define DIMC  1024
#define NHEAD 16
#define HD    64
#define SCALE 0.125f            // 64^-0.5

#define M_TOT (BATCH*SEQ)       // 4096
#define QKV_N (3*DIMC)          // 3072

// Pre-split bf16 hi/lo scratch (allocation-free rule: __device__ globals)
__device__ __nv_bfloat16 g_xh [(size_t)M_TOT * DIMC],  g_xl [(size_t)M_TOT * DIMC];
__device__ __nv_bfloat16 g_wqh[(size_t)QKV_N * DIMC],  g_wql[(size_t)QKV_N * DIMC];
__device__ __nv_bfloat16 g_wph[(size_t)DIMC * DIMC],   g_wpl[(size_t)DIMC * DIMC];
__device__ __nv_bfloat16 g_qh [(size_t)M_TOT * QKV_N], g_ql [(size_t)M_TOT * QKV_N];
__device__ __nv_bfloat16 g_aoh[(size_t)M_TOT * DIMC],  g_aol[(size_t)M_TOT * DIMC];

// ===========================================================================
// Primitives
// ===========================================================================
__device__ __forceinline__ uint32_t smem_u32(const void* p) {
    uint32_t a;
    asm("{ .reg .u64 t; cvta.to.shared.u64 t, %1; cvt.u32.u64 %0, t; }" : "=r"(a) : "l"(p));
    return a;
}
__device__ __forceinline__ void ldsm_x4(uint32_t* r, uint32_t addr) {
    asm volatile("ldmatrix.sync.aligned.m8n8.x4.shared.b16 {%0,%1,%2,%3}, [%4];"
        : "=r"(r[0]), "=r"(r[1]), "=r"(r[2]), "=r"(r[3]) : "r"(addr));
}
__device__ __forceinline__ void ldsm_x4_t(uint32_t* r, uint32_t addr) {
    asm volatile("ldmatrix.sync.aligned.m8n8.x4.trans.shared.b16 {%0,%1,%2,%3}, [%4];"
        : "=r"(r[0]), "=r"(r[1]), "=r"(r[2]), "=r"(r[3]) : "r"(addr));
}
__device__ __forceinline__ void mma_bf16(float* d, const uint32_t* a, uint32_t b0, uint32_t b1) {
    asm volatile(
        "mma.sync.aligned.m16n8k16.row.col.f32.bf16.bf16.f32 "
        "{%0,%1,%2,%3}, {%4,%5,%6,%7}, {%8,%9}, {%0,%1,%2,%3};"
        : "+f"(d[0]), "+f"(d[1]), "+f"(d[2]), "+f"(d[3])
        : "r"(a[0]), "r"(a[1]), "r"(a[2]), "r"(a[3]), "r"(b0), "r"(b1));
}
__device__ __forceinline__ uint32_t packbf(float lo, float hi) {
    __nv_bfloat162 t = __floats2bfloat162_rn(lo, hi);
    return *reinterpret_cast<uint32_t*>(&t);
}
#define CP16(dst, src) \
    asm volatile("cp.async.cg.shared.global [%0], [%1], 16;" \
        :: "r"(dst), "l"(__cvta_generic_to_global(src)) : "memory")
#define CP_COMMIT() asm volatile("cp.async.commit_group;" ::: "memory")
#define CP_WAIT0()  asm volatile("cp.async.wait_group 0;" ::: "memory")

// ===========================================================================
// Split prepass: fp32 -> bf16 hi + bf16 lo (elementwise, vectorized)
// ===========================================================================
__global__ __launch_bounds__(256) void split32(
    const float* __restrict__ in, __nv_bfloat16* __restrict__ hi,
    __nv_bfloat16* __restrict__ lo, int n)
{
    int i = (blockIdx.x * 256 + threadIdx.x) * 4;
    if (i >= n) return;
    float4 v = *(const float4*)(in + i);
    float h0 = __bfloat162float(__float2bfloat16_rn(v.x));
    float h1 = __bfloat162float(__float2bfloat16_rn(v.y));
    float h2 = __bfloat162float(__float2bfloat16_rn(v.z));
    float h3 = __bfloat162float(__float2bfloat16_rn(v.w));
    *(uint2*)(hi + i) = make_uint2(packbf(h0, h1), packbf(h2, h3));
    *(uint2*)(lo + i) = make_uint2(packbf(v.x - h0, v.y - h1), packbf(v.z - h2, v.w - h3));
}

// ===========================================================================
// bf16x3 split GEMM-NT, cp.async pipelined.
// C[M,N] = (Ah+Al)[M,K] * (Bh+Bl)[N,K]^T (dropping Al*Bl).
// 128x128 CTA tile, K-chunk 64, 2-stage cp.async smem pipeline.
// Output: fp32 C, or split bf16 (Ch,Cl) if C == nullptr.
// ===========================================================================
#define TILE_B 16384                    // 128 rows x 128 bytes (64 bf16)
#define BUF_B  (4 * TILE_B)             // Ah, Al, Bh, Bl
#define GEMM_SMEM (2 * BUF_B)           // 131072 B

__global__ __launch_bounds__(256) void gemm_split(
    const __nv_bfloat16* __restrict__ Ah, const __nv_bfloat16* __restrict__ Al,
    const __nv_bfloat16* __restrict__ Bh, const __nv_bfloat16* __restrict__ Bl,
    float* __restrict__ C, __nv_bfloat16* __restrict__ Ch, __nv_bfloat16* __restrict__ Cl,
    int M, int N, int K)
{
    extern __shared__ char smem[];
    const uint32_t sbase = smem_u32(smem);
    const int tid  = threadIdx.x;
    const int wid  = tid >> 5;
    const int lane = tid & 31;
    const int bm = blockIdx.y * 128;
    const int bn = blockIdx.x * 128;

    const int warpM = (wid & 1) * 64;
    const int warpN = (wid >> 1) * 32;
    const int lrow = lane & 15;
    const int kb   = (lane >> 4) * 16;

    uint32_t aRow[4], aSwz[4];
#pragma unroll
    for (int mi = 0; mi < 4; mi++) {
        int r = warpM + mi * 16 + lrow;
        aRow[mi] = (uint32_t)(r * 128);
        aSwz[mi] = (uint32_t)((r & 7) << 4);
    }
    uint32_t bRow[2], bSwz[2];
#pragma unroll
    for (int nj = 0; nj < 2; nj++) {
        int r = warpN + nj * 16 + lrow;
        bRow[nj] = (uint32_t)(r * 128);
        bSwz[nj] = (uint32_t)((r & 7) << 4);
    }

    // cp.async staging: thread -> row tid>>1, 4 16B chunks in half (tid&1)
    const int crow = tid >> 1;
    const int chalf = tid & 1;
    uint32_t stC[4];
#pragma unroll
    for (int j = 0; j < 4; j++) {
        uint32_t off = (uint32_t)(crow * 128 + (chalf * 4 + j) * 16);
        stC[j] = off ^ ((off >> 3) & 0x70);
    }
    const size_t aoff = (size_t)(bm + crow) * K + chalf * 32;
    const size_t boff = (size_t)(bn + crow) * K + chalf * 32;

    float acc[4][4][4];
#pragma unroll
    for (int mi = 0; mi < 4; mi++)
#pragma unroll
        for (int nj = 0; nj < 4; nj++)
#pragma unroll
            for (int k = 0; k < 4; k++) acc[mi][nj][k] = 0.f;

    const int nch = K >> 6;

    // prologue: stage chunk 0
    {
        const uint32_t s0 = sbase;
#pragma unroll
        for (int j = 0; j < 4; j++) {
            CP16(s0 + 0*TILE_B + stC[j], Ah + aoff + j * 8);
            CP16(s0 + 1*TILE_B + stC[j], Al + aoff + j * 8);
            CP16(s0 + 2*TILE_B + stC[j], Bh + boff + j * 8);
            CP16(s0 + 3*TILE_B + stC[j], Bl + boff + j * 8);
        }
        CP_COMMIT();
    }

    for (int ch = 0; ch < nch; ch++) {
        CP_WAIT0();
        __syncthreads();

        // prefetch next chunk into the other stage (overlaps with MMA below)
        if (ch + 1 < nch) {
            const uint32_t s1 = sbase + (uint32_t)((ch + 1) & 1) * BUF_B;
            const size_t ka = aoff + (size_t)(ch + 1) * 64;
            const size_t kbo = boff + (size_t)(ch + 1) * 64;
#pragma unroll
            for (int j = 0; j < 4; j++) {
                CP16(s1 + 0*TILE_B + stC[j], Ah + ka + j * 8);
                CP16(s1 + 1*TILE_B + stC[j], Al + ka + j * 8);
                CP16(s1 + 2*TILE_B + stC[j], Bh + kbo + j * 8);
                CP16(s1 + 3*TILE_B + stC[j], Bl + kbo + j * 8);
            }
            CP_COMMIT();
        }

        const uint32_t bufb = sbase + (uint32_t)(ch & 1) * BUF_B;
#pragma unroll
        for (int ks = 0; ks < 4; ks++) {
            const uint32_t koff = (uint32_t)(ks * 32 + kb);
            uint32_t ah[4][4], al[4][4], bh[2][4], bl[2][4];
#pragma unroll
            for (int mi = 0; mi < 4; mi++)
                ldsm_x4(ah[mi], bufb + 0*TILE_B + aRow[mi] + (koff ^ aSwz[mi]));
#pragma unroll
            for (int nj = 0; nj < 2; nj++)
                ldsm_x4(bh[nj], bufb + 2*TILE_B + bRow[nj] + (koff ^ bSwz[nj]));
#pragma unroll
            for (int mi = 0; mi < 4; mi++)
#pragma unroll
                for (int nj = 0; nj < 4; nj++)
                    mma_bf16(acc[mi][nj], ah[mi], bh[nj>>1][nj&1], bh[nj>>1][(nj&1)+2]);
#pragma unroll
            for (int nj = 0; nj < 2; nj++)
                ldsm_x4(bl[nj], bufb + 3*TILE_B + bRow[nj] + (koff ^ bSwz[nj]));
#pragma unroll
            for (int mi = 0; mi < 4; mi++)
#pragma unroll
                for (int nj = 0; nj < 4; nj++)
                    mma_bf16(acc[mi][nj], ah[mi], bl[nj>>1][nj&1], bl[nj>>1][(nj&1)+2]);
#pragma unroll
            for (int mi = 0; mi < 4; mi++)
                ldsm_x4(al[mi], bufb + 1*TILE_B + aRow[mi] + (koff ^ aSwz[mi]));
#pragma unroll
            for (int mi = 0; mi < 4; mi++)
#pragma unroll
                for (int nj = 0; nj < 4; nj++)
                    mma_bf16(acc[mi][nj], al[mi], bh[nj>>1][nj&1], bh[nj>>1][(nj&1)+2]);
        }
        __syncthreads();
    }

    const int er = lane >> 2;
    const int ec = (lane & 3) * 2;
    if (C) {
#pragma unroll
        for (int mi = 0; mi < 4; mi++) {
            const int r0 = bm + warpM + mi * 16 + er;
#pragma unroll
            for (int nj = 0; nj < 4; nj++) {
                const int c = bn + warpN + nj * 8 + ec;
                *(float2*)&C[(size_t)r0 * N + c]       = make_float2(acc[mi][nj][0], acc[mi][nj][1]);
                *(float2*)&C[(size_t)(r0 + 8) * N + c] = make_float2(acc[mi][nj][2], acc[mi][nj][3]);
            }
        }
    } else {
#pragma unroll
        for (int mi = 0; mi < 4; mi++) {
            const int r0 = bm + warpM + mi * 16 + er;
#pragma unroll
            for (int nj = 0; nj < 4; nj++) {
                const int c = bn + warpN + nj * 8 + ec;
                float v0 = acc[mi][nj][0], v1 = acc[mi][nj][1];
                float v2 = acc[mi][nj][2], v3 = acc[mi][nj][3];
                float h0 = __bfloat162float(__float2bfloat16_rn(v0));
                float h1 = __bfloat162float(__float2bfloat16_rn(v1));
                float h2 = __bfloat162float(__float2bfloat16_rn(v2));
                float h3 = __bfloat162float(__float2bfloat16_rn(v3));
                *(uint32_t*)&Ch[(size_t)r0 * N + c]       = packbf(h0, h1);
                *(uint32_t*)&Cl[(size_t)r0 * N + c]       = packbf(v0 - h0, v1 - h1);
                *(uint32_t*)&Ch[(size_t)(r0 + 8) * N + c] = packbf(h2, h3);
                *(uint32_t*)&Cl[(size_t)(r0 + 8) * N + c] = packbf(v2 - h2, v3 - h3);
            }
        }
    }
}

// ===========================================================================
// Tensor-core flash attention over pre-split bf16 qkv, cp.async pipelined.
// BQ=128 (warp = 16 rows), BK=128, HD=64, 256 threads, 2-stage KV buffers.
// ===========================================================================
#define FA_STAGE (4 * 16384)            // KH, KL, VH, VL
#define FA_SMEM  (2 * FA_STAGE)         // 131072 B

__global__ __launch_bounds__(256) void flash_split(
    const __nv_bfloat16* __restrict__ qh_g, const __nv_bfloat16* __restrict__ ql_g,
    const float* __restrict__ head_w,
    __nv_bfloat16* __restrict__ aoh, __nv_bfloat16* __restrict__ aol)
{
    extern __shared__ char smem[];
    const uint32_t sb = smem_u32(smem);

    const int tid  = threadIdx.x;
    const int wid  = tid >> 5;
    const int lane = tid & 31;
    const int q0 = blockIdx.x * 128;
    const int h  = blockIdx.y;
    const int b  = blockIdx.z;

    float hw;
    {
        float mx = -1e30f;
#pragma unroll
        for (int i = 0; i < NHEAD; i++) mx = fmaxf(mx, head_w[i]);
        float ssum = 0.f;
#pragma unroll
        for (int i = 0; i < NHEAD; i++) ssum += __expf(head_w[i] - mx);
        hw = __expf(head_w[h] - mx) / ssum;
    }

    // cp.async staging geometry
    const int crow = tid >> 1;
    const int chalf = tid & 1;
    uint32_t stC[4];
#pragma unroll
    for (int j = 0; j < 4; j++) {
        uint32_t off = (uint32_t)(crow * 128 + (chalf * 4 + j) * 16);
        stC[j] = off ^ ((off >> 3) & 0x70);
    }

    // ---- stage Q (hi, lo) into stage-0 KH/KL slots, load fragments ----
    {
        const size_t qoff = (size_t)(b * SEQ + q0 + crow) * 3 * DIMC + h * HD + chalf * 32;
#pragma unroll
        for (int j = 0; j < 4; j++) {
            CP16(sb + 0*16384 + stC[j], qh_g + qoff + j * 8);
            CP16(sb + 1*16384 + stC[j], ql_g + qoff + j * 8);
        }
        CP_COMMIT();
        CP_WAIT0();
        __syncthreads();
    }

    const int lrow = lane & 15;
    const int kb   = (lane >> 4) * 16;
    const uint32_t aOff = (uint32_t)((wid * 16 + lrow) * 128);
    const uint32_t aSwz = (uint32_t)((lrow & 7) << 4);

    uint32_t qh[4][4], ql[4][4];
#pragma unroll
    for (int ks = 0; ks < 4; ks++) {
        const uint32_t koff = (uint32_t)(ks * 32 + kb);
        ldsm_x4(qh[ks], sb + 0*16384 + aOff + (koff ^ aSwz));
        ldsm_x4(ql[ks], sb + 1*16384 + aOff + (koff ^ aSwz));
    }
    __syncthreads();   // done reading Q from stage 0 before KV overwrites it

    // KV tile issue (stage s): KH,KL,VH,VL
    const size_t kvrow_base = (size_t)(b * SEQ + crow) * 3 * DIMC + h * HD + chalf * 32;
    // + kt*128*3*DIMC per tile; +1*DIMC for K, +2*DIMC for V

    {   // prologue: KV tile 0 -> stage 0
        const size_t k0 = kvrow_base + (size_t)1 * DIMC;
        const size_t v0 = kvrow_base + (size_t)2 * DIMC;
#pragma unroll
        for (int j = 0; j < 4; j++) {
            CP16(sb + 0*16384 + stC[j], qh_g + k0 + j * 8);
            CP16(sb + 1*16384 + stC[j], ql_g + k0 + j * 8);
            CP16(sb + 2*16384 + stC[j], qh_g + v0 + j * 8);
            CP16(sb + 3*16384 + stC[j], ql_g + v0 + j * 8);
        }
        CP_COMMIT();
    }

    uint32_t bOff[8];
#pragma unroll
    for (int g = 0; g < 8; g++) bOff[g] = (uint32_t)((g * 16 + lrow) * 128);
    const uint32_t bSwz = (uint32_t)((lrow & 7) << 4);
    const uint32_t vRowBase = (uint32_t)(lane & 15);
    const uint32_t vColPart = (uint32_t)((lane >> 4) * 16);

    float m_r[2] = {-1e30f, -1e30f};
    float l_r[2] = {0.f, 0.f};
    float o[8][4];
#pragma unroll
    for (int g = 0; g < 8; g++)
#pragma unroll
        for (int e = 0; e < 4; e++) o[g][e] = 0.f;

    for (int kt = 0; kt < SEQ / 128; kt++) {
        CP_WAIT0();
        __syncthreads();

        // prefetch next KV tile into other stage
        if (kt + 1 < SEQ / 128) {
            const uint32_t s1 = sb + (uint32_t)((kt + 1) & 1) * FA_STAGE;
            const size_t kn = kvrow_base + (size_t)(kt + 1) * 128 * 3 * DIMC + (size_t)1 * DIMC;
            const size_t vn = kvrow_base + (size_t)(kt + 1) * 128 * 3 * DIMC + (size_t)2 * DIMC;
#pragma unroll
            for (int j = 0; j < 4; j++) {
                CP16(s1 + 0*16384 + stC[j], qh_g + kn + j * 8);
                CP16(s1 + 1*16384 + stC[j], ql_g + kn + j * 8);
                CP16(s1 + 2*16384 + stC[j], qh_g + vn + j * 8);
                CP16(s1 + 3*16384 + stC[j], ql_g + vn + j * 8);
            }
            CP_COMMIT();
        }

        const uint32_t sKH = sb + (uint32_t)(kt & 1) * FA_STAGE;
        const uint32_t sKL = sKH + 16384;
        const uint32_t sVH = sKH + 32768;
        const uint32_t sVL = sKH + 49152;

        // ---- S = Q K^T (bf16x3) ----
        float s[16][4];
#pragma unroll
        for (int nj = 0; nj < 16; nj++)
#pragma unroll
            for (int e = 0; e < 4; e++) s[nj][e] = 0.f;

#pragma unroll
        for (int ks = 0; ks < 4; ks++) {
            const uint32_t koff = (uint32_t)(ks * 32 + kb);
#pragma unroll
            for (int g = 0; g < 8; g++) {
                uint32_t kh4[4], kl4[4];
                ldsm_x4(kh4, sKH + bOff[g] + (koff ^ bSwz));
                ldsm_x4(kl4, sKL + bOff[g] + (koff ^ bSwz));
                mma_bf16(s[2*g],   qh[ks], kh4[0], kh4[2]);
                mma_bf16(s[2*g+1], qh[ks], kh4[1], kh4[3]);
                mma_bf16(s[2*g],   qh[ks], kl4[0], kl4[2]);
                mma_bf16(s[2*g+1], qh[ks], kl4[1], kl4[3]);
                mma_bf16(s[2*g],   ql[ks], kh4[0], kh4[2]);
                mma_bf16(s[2*g+1], ql[ks], kh4[1], kh4[3]);
            }
        }

        // ---- online softmax ----
        float mx0 = -1e30f, mx1 = -1e30f;
#pragma unroll
        for (int nj = 0; nj < 16; nj++) {
            s[nj][0] *= SCALE; s[nj][1] *= SCALE; s[nj][2] *= SCALE; s[nj][3] *= SCALE;
            mx0 = fmaxf(mx0, fmaxf(s[nj][0], s[nj][1]));
            mx1 = fmaxf(mx1, fmaxf(s[nj][2], s[nj][3]));
        }
        mx0 = fmaxf(mx0, __shfl_xor_sync(0xffffffffu, mx0, 1));
        mx0 = fmaxf(mx0, __shfl_xor_sync(0xffffffffu, mx0, 2));
        mx1 = fmaxf(mx1, __shfl_xor_sync(0xffffffffu, mx1, 1));
        mx1 = fmaxf(mx1, __shfl_xor_sync(0xffffffffu, mx1, 2));
        const float mn0 = fmaxf(m_r[0], mx0);
        const float mn1 = fmaxf(m_r[1], mx1);
        const float alpha0 = __expf(m_r[0] - mn0);
        const float alpha1 = __expf(m_r[1] - mn1);
        m_r[0] = mn0; m_r[1] = mn1;
        float sum0 = 0.f, sum1 = 0.f;
#pragma unroll
        for (int nj = 0; nj < 16; nj++) {
            s[nj][0] = __expf(s[nj][0] - mn0); sum0 += s[nj][0];
            s[nj][1] = __expf(s[nj][1] - mn0); sum0 += s[nj][1];
            s[nj][2] = __expf(s[nj][2] - mn1); sum1 += s[nj][2];
            s[nj][3] = __expf(s[nj][3] - mn1); sum1 += s[nj][3];
        }
        sum0 += __shfl_xor_sync(0xffffffffu, sum0, 1);
        sum0 += __shfl_xor_sync(0xffffffffu, sum0, 2);
        sum1 += __shfl_xor_sync(0xffffffffu, sum1, 1);
        sum1 += __shfl_xor_sync(0xffffffffu, sum1, 2);
        l_r[0] = l_r[0] * alpha0 + sum0;
        l_r[1] = l_r[1] * alpha1 + sum1;
#pragma unroll
        for (int g = 0; g < 8; g++) {
            o[g][0] *= alpha0; o[g][1] *= alpha0;
            o[g][2] *= alpha1; o[g][3] *= alpha1;
        }

        // ---- O += P V (bf16x3) ----
#pragma unroll
        for (int t = 0; t < 8; t++) {
            uint32_t pa_h[4], pa_l[4];
            {
                float e0 = s[2*t][0], e1 = s[2*t][1], e2 = s[2*t][2], e3 = s[2*t][3];
                float f0 = s[2*t+1][0], f1 = s[2*t+1][1], f2 = s[2*t+1][2], f3 = s[2*t+1][3];
                float h0 = __bfloat162float(__float2bfloat16_rn(e0));
                float h1 = __bfloat162float(__float2bfloat16_rn(e1));
                float h2 = __bfloat162float(__float2bfloat16_rn(e2));
                float h3 = __bfloat162float(__float2bfloat16_rn(e3));
                float g0 = __bfloat162float(__float2bfloat16_rn(f0));
                float g1 = __bfloat162float(__float2bfloat16_rn(f1));
                float g2 = __bfloat162float(__float2bfloat16_rn(f2));
                float g3 = __bfloat162float(__float2bfloat16_rn(f3));
                pa_h[0] = packbf(h0, h1); pa_h[1] = packbf(h2, h3);
                pa_h[2] = packbf(g0, g1); pa_h[3] = packbf(g2, g3);
                pa_l[0] = packbf(e0-h0, e1-h1); pa_l[1] = packbf(e2-h2, e3-h3);
                pa_l[2] = packbf(f0-g0, f1-g1); pa_l[3] = packbf(f2-g2, f3-g3);
            }
#pragma unroll
            for (int g = 0; g < 4; g++) {
                const uint32_t vr = (uint32_t)(16 * t) + vRowBase;
                const uint32_t vc = (uint32_t)(g * 32) + vColPart;
                const uint32_t voff = vr * 128 + (vc ^ ((vr & 7) << 4));
                uint32_t vh4[4], vl4[4];
                ldsm_x4_t(vh4, sVH + voff);
                ldsm_x4_t(vl4, sVL + voff);
                mma_bf16(o[2*g],   pa_h, vh4[0], vh4[1]);
                mma_bf16(o[2*g+1], pa_h, vh4[2], vh4[3]);
                mma_bf16(o[2*g],   pa_h, vl4[0], vl4[1]);
                mma_bf16(o[2*g+1], pa_h, vl4[2], vl4[3]);
                mma_bf16(o[2*g],   pa_l, vh4[0], vh4[1]);
                mma_bf16(o[2*g+1], pa_l, vh4[2], vh4[3]);
            }
        }
    }

    // ---- epilogue: O/l * hw -> split bf16 ao ----
    const int er = lane >> 2;
    const int ec = (lane & 3) * 2;
    const float inv0 = hw / l_r[0];
    const float inv1 = hw / l_r[1];
    const int r0 = q0 + wid * 16 + er;
#pragma unroll
    for (int g = 0; g < 8; g++) {
        const int d = h * HD + g * 8 + ec;
        float f0 = o[g][0] * inv0, f1 = o[g][1] * inv0;
        float f2 = o[g][2] * inv1, f3 = o[g][3] * inv1;
        float h0 = __bfloat162float(__float2bfloat16_rn(f0));
        float h1 = __bfloat162float(__float2bfloat16_rn(f1));
        float h2 = __bfloat162float(__float2bfloat16_rn(f2));
        float h3 = __bfloat162float(__float2bfloat16_rn(f3));
        const size_t i0 = (size_t)(b * SEQ + r0) * DIMC + d;
        const size_t i1 = (size_t)(b * SEQ + r0 + 8) * DIMC + d;
        *(uint32_t*)&aoh[i0] = packbf(h0, h1);
        *(uint32_t*)&aol[i0] = packbf(f0 - h0, f1 - h1);
        *(uint32_t*)&aoh[i1] = packbf(h2, h3);
        *(uint32_t*)&aol[i1] = packbf(f2 - h2, f3 - h3);
    }
}

// ===========================================================================
extern "C" void kernel_launch(void* const* d_in, const int* in_sizes, int n_in,
                              void* d_out, int out_size)
{
    const float* x      = (const float*)d_in[0];
    const float* w_qkv  = (const float*)d_in[1];
    const float* w_proj = (const float*)d_in[2];
    const float* head_w = (const float*)d_in[3];
    float* out = (float*)d_out;

    __nv_bfloat16 *xh, *xl, *wqh, *wql, *wph, *wpl, *qh, *ql, *aoh, *aol;
    cudaGetSymbolAddress((void**)&xh,  g_xh);  cudaGetSymbolAddress((void**)&xl,  g_xl);
    cudaGetSymbolAddress((void**)&wqh, g_wqh); cudaGetSymbolAddress((void**)&wql, g_wql);
    cudaGetSymbolAddress((void**)&wph, g_wph); cudaGetSymbolAddress((void**)&wpl, g_wpl);
    cudaGetSymbolAddress((void**)&qh,  g_qh);  cudaGetSymbolAddress((void**)&ql,  g_ql);
    cudaGetSymbolAddress((void**)&aoh, g_aoh); cudaGetSymbolAddress((void**)&aol, g_aol);

    cudaFuncSetAttribute(gemm_split, cudaFuncAttributeMaxDynamicSharedMemorySize, GEMM_SMEM);
    cudaFuncSetAttribute(flash_split, cudaFuncAttributeMaxDynamicSharedMemorySize, FA_SMEM);

    // 0) split prepass
    split32<<<(M_TOT * DIMC) / 1024, 256>>>(x, xh, xl, M_TOT * DIMC);
    split32<<<(QKV_N * DIMC) / 1024, 256>>>(w_qkv, wqh, wql, QKV_N * DIMC);
    split32<<<(DIMC * DIMC) / 1024, 256>>>(w_proj, wph, wpl, DIMC * DIMC);

    // 1) QKV projection -> split bf16 qkv
    dim3 g1(QKV_N / 128, M_TOT / 128);
    gemm_split<<<g1, 256, GEMM_SMEM>>>(xh, xl, wqh, wql, nullptr, qh, ql,
                                       M_TOT, QKV_N, DIMC);

    // 2) flash attention + head weights -> split bf16 ao
    dim3 g2(SEQ / 128, NHEAD, BATCH);
    flash_split<<<g2, 256, FA_SMEM>>>(qh, ql, head_w, aoh, aol);

    // 3) output projection -> fp32 out
    dim3 g3(DIMC / 128, M_TOT / 128);
    gemm_split<<<g3, 256, GEMM_SMEM>>>(aoh, aol, wph, wpl, out, nullptr, nullptr,
                                       M_TOT, DIMC, DIMC);
}

// round 8
// speedup vs baseline: 2.4631x; 1.1394x over previous
#include <cuda_runtime.h>
#include <cuda_bf16.h>
#include <cstdint>

#define BATCH 2
#define SEQ   2048
#define DIMC  1024
#define NHEAD 16
#define HD    64
#define SCALE 0.125f            // 64^-0.5

#define M_TOT (BATCH*SEQ)       // 4096
#define QKV_N (3*DIMC)          // 3072

// Pre-split bf16 hi/lo scratch (allocation-free rule: __device__ globals)
__device__ __nv_bfloat16 g_xh [(size_t)M_TOT * DIMC],  g_xl [(size_t)M_TOT * DIMC];
__device__ __nv_bfloat16 g_wqh[(size_t)QKV_N * DIMC],  g_wql[(size_t)QKV_N * DIMC];
__device__ __nv_bfloat16 g_wph[(size_t)DIMC * DIMC],   g_wpl[(size_t)DIMC * DIMC];
__device__ __nv_bfloat16 g_qh [(size_t)M_TOT * QKV_N], g_ql [(size_t)M_TOT * QKV_N];
__device__ __nv_bfloat16 g_aoh[(size_t)M_TOT * DIMC],  g_aol[(size_t)M_TOT * DIMC];

// ===========================================================================
// Primitives
// ===========================================================================
__device__ __forceinline__ uint32_t smem_u32(const void* p) {
    uint32_t a;
    asm("{ .reg .u64 t; cvta.to.shared.u64 t, %1; cvt.u32.u64 %0, t; }" : "=r"(a) : "l"(p));
    return a;
}
__device__ __forceinline__ void ldsm_x4(uint32_t* r, uint32_t addr) {
    asm volatile("ldmatrix.sync.aligned.m8n8.x4.shared.b16 {%0,%1,%2,%3}, [%4];"
        : "=r"(r[0]), "=r"(r[1]), "=r"(r[2]), "=r"(r[3]) : "r"(addr));
}
__device__ __forceinline__ void ldsm_x4_t(uint32_t* r, uint32_t addr) {
    asm volatile("ldmatrix.sync.aligned.m8n8.x4.trans.shared.b16 {%0,%1,%2,%3}, [%4];"
        : "=r"(r[0]), "=r"(r[1]), "=r"(r[2]), "=r"(r[3]) : "r"(addr));
}
__device__ __forceinline__ void mma_bf16(float* d, const uint32_t* a, uint32_t b0, uint32_t b1) {
    asm volatile(
        "mma.sync.aligned.m16n8k16.row.col.f32.bf16.bf16.f32 "
        "{%0,%1,%2,%3}, {%4,%5,%6,%7}, {%8,%9}, {%0,%1,%2,%3};"
        : "+f"(d[0]), "+f"(d[1]), "+f"(d[2]), "+f"(d[3])
        : "r"(a[0]), "r"(a[1]), "r"(a[2]), "r"(a[3]), "r"(b0), "r"(b1));
}
__device__ __forceinline__ uint32_t packbf(float lo, float hi) {
    __nv_bfloat162 t = __floats2bfloat162_rn(lo, hi);
    return *reinterpret_cast<uint32_t*>(&t);
}
#define CP16(dst, src) \
    asm volatile("cp.async.cg.shared.global [%0], [%1], 16;" \
        :: "r"(dst), "l"(__cvta_generic_to_global(src)) : "memory")
#define CP_COMMIT() asm volatile("cp.async.commit_group;" ::: "memory")
#define CP_WAIT0()  asm volatile("cp.async.wait_group 0;" ::: "memory")
#define CP_WAIT1()  asm volatile("cp.async.wait_group 1;" ::: "memory")

// ===========================================================================
// Split prepass: fp32 -> bf16 hi + bf16 lo
// ===========================================================================
__global__ __launch_bounds__(256) void split32(
    const float* __restrict__ in, __nv_bfloat16* __restrict__ hi,
    __nv_bfloat16* __restrict__ lo, int n)
{
    int i = (blockIdx.x * 256 + threadIdx.x) * 4;
    if (i >= n) return;
    float4 v = *(const float4*)(in + i);
    float h0 = __bfloat162float(__float2bfloat16_rn(v.x));
    float h1 = __bfloat162float(__float2bfloat16_rn(v.y));
    float h2 = __bfloat162float(__float2bfloat16_rn(v.z));
    float h3 = __bfloat162float(__float2bfloat16_rn(v.w));
    *(uint2*)(hi + i) = make_uint2(packbf(h0, h1), packbf(h2, h3));
    *(uint2*)(lo + i) = make_uint2(packbf(v.x - h0, v.y - h1), packbf(v.z - h2, v.w - h3));
}

// ===========================================================================
// bf16x3 split GEMM-NT, cp.async 3-stage pipeline, K-chunk 32, 2 CTAs/SM.
// C[M,N] = (Ah+Al)(Bh+Bl)^T minus Al*Bl. 128x128 CTA tile.
// 64B smem rows, SW64 swizzle (conflict-free ldmatrix).
// ===========================================================================
#define CHK    32
#define TILE2  8192                      // 128 rows x 64 bytes
#define STG_B  (4 * TILE2)               // Ah, Al, Bh, Bl = 32KB
#define NSTG   3
#define GEMM_SMEM (NSTG * STG_B)         // 98304 B

__global__ __launch_bounds__(256, 2) void gemm_split(
    const __nv_bfloat16* __restrict__ Ah, const __nv_bfloat16* __restrict__ Al,
    const __nv_bfloat16* __restrict__ Bh, const __nv_bfloat16* __restrict__ Bl,
    float* __restrict__ C, __nv_bfloat16* __restrict__ Ch, __nv_bfloat16* __restrict__ Cl,
    int M, int N, int K)
{
    extern __shared__ char smem[];
    const uint32_t sbase = smem_u32(smem);
    const int tid  = threadIdx.x;
    const int wid  = tid >> 5;
    const int lane = tid & 31;
    const int bm = blockIdx.y * 128;
    const int bn = blockIdx.x * 128;

    const int warpM = (wid & 1) * 64;
    const int warpN = (wid >> 1) * 32;
    const int lrow = lane & 15;
    const int kb   = (lane >> 4) * 16;

    uint32_t aRow[4], aSwz[4];
#pragma unroll
    for (int mi = 0; mi < 4; mi++) {
        int r = warpM + mi * 16 + lrow;
        aRow[mi] = (uint32_t)(r * 64);
        aSwz[mi] = (uint32_t)((r & 6) << 3);
    }
    uint32_t bRow[2], bSwz[2];
#pragma unroll
    for (int nj = 0; nj < 2; nj++) {
        int r = warpN + nj * 16 + lrow;
        bRow[nj] = (uint32_t)(r * 64);
        bSwz[nj] = (uint32_t)((r & 6) << 3);
    }

    // staging: thread -> row tid>>1, half (tid&1): 2 16B chunks per tile
    const int crow = tid >> 1;
    const int chalf = tid & 1;
    uint32_t stC[2];
#pragma unroll
    for (int j = 0; j < 2; j++) {
        uint32_t off = (uint32_t)(crow * 64 + (chalf * 2 + j) * 16);
        stC[j] = off ^ ((off >> 3) & 0x30);
    }
    const size_t aoff = (size_t)(bm + crow) * K + chalf * 16;
    const size_t boff = (size_t)(bn + crow) * K + chalf * 16;

    float acc[4][4][4];
#pragma unroll
    for (int mi = 0; mi < 4; mi++)
#pragma unroll
        for (int nj = 0; nj < 4; nj++)
#pragma unroll
            for (int k = 0; k < 4; k++) acc[mi][nj][k] = 0.f;

    const int nch = K / CHK;             // 32 for K=1024

    // prologue: issue chunks 0 and 1
#pragma unroll
    for (int p = 0; p < NSTG - 1; p++) {
        const uint32_t s = sbase + (uint32_t)p * STG_B;
        const size_t ka = aoff + (size_t)p * CHK;
        const size_t kbo = boff + (size_t)p * CHK;
#pragma unroll
        for (int j = 0; j < 2; j++) {
            CP16(s + 0*TILE2 + stC[j], Ah + ka + j * 8);
            CP16(s + 1*TILE2 + stC[j], Al + ka + j * 8);
            CP16(s + 2*TILE2 + stC[j], Bh + kbo + j * 8);
            CP16(s + 3*TILE2 + stC[j], Bl + kbo + j * 8);
        }
        CP_COMMIT();
    }

    for (int ch = 0; ch < nch; ch++) {
        if (ch + 1 < nch) CP_WAIT1(); else CP_WAIT0();
        __syncthreads();

        if (ch + 2 < nch) {
            const uint32_t s = sbase + (uint32_t)((ch + 2) % NSTG) * STG_B;
            const size_t ka = aoff + (size_t)(ch + 2) * CHK;
            const size_t kbo = boff + (size_t)(ch + 2) * CHK;
#pragma unroll
            for (int j = 0; j < 2; j++) {
                CP16(s + 0*TILE2 + stC[j], Ah + ka + j * 8);
                CP16(s + 1*TILE2 + stC[j], Al + ka + j * 8);
                CP16(s + 2*TILE2 + stC[j], Bh + kbo + j * 8);
                CP16(s + 3*TILE2 + stC[j], Bl + kbo + j * 8);
            }
            CP_COMMIT();
        }

        const uint32_t bufb = sbase + (uint32_t)(ch % NSTG) * STG_B;
#pragma unroll
        for (int ks = 0; ks < 2; ks++) {
            const uint32_t koff = (uint32_t)(ks * 32 + kb);
            uint32_t ah[4][4], bh[2][4];
#pragma unroll
            for (int mi = 0; mi < 4; mi++)
                ldsm_x4(ah[mi], bufb + 0*TILE2 + aRow[mi] + (koff ^ aSwz[mi]));
#pragma unroll
            for (int nj = 0; nj < 2; nj++)
                ldsm_x4(bh[nj], bufb + 2*TILE2 + bRow[nj] + (koff ^ bSwz[nj]));
#pragma unroll
            for (int mi = 0; mi < 4; mi++)
#pragma unroll
                for (int nj = 0; nj < 4; nj++)
                    mma_bf16(acc[mi][nj], ah[mi], bh[nj>>1][nj&1], bh[nj>>1][(nj&1)+2]);
            {
                uint32_t bl[2][4];
#pragma unroll
                for (int nj = 0; nj < 2; nj++)
                    ldsm_x4(bl[nj], bufb + 3*TILE2 + bRow[nj] + (koff ^ bSwz[nj]));
#pragma unroll
                for (int mi = 0; mi < 4; mi++)
#pragma unroll
                    for (int nj = 0; nj < 4; nj++)
                        mma_bf16(acc[mi][nj], ah[mi], bl[nj>>1][nj&1], bl[nj>>1][(nj&1)+2]);
            }
            {
                uint32_t al[4][4];
#pragma unroll
                for (int mi = 0; mi < 4; mi++)
                    ldsm_x4(al[mi], bufb + 1*TILE2 + aRow[mi] + (koff ^ aSwz[mi]));
#pragma unroll
                for (int mi = 0; mi < 4; mi++)
#pragma unroll
                    for (int nj = 0; nj < 4; nj++)
                        mma_bf16(acc[mi][nj], al[mi], bh[nj>>1][nj&1], bh[nj>>1][(nj&1)+2]);
            }
        }
    }

    const int er = lane >> 2;
    const int ec = (lane & 3) * 2;
    if (C) {
#pragma unroll
        for (int mi = 0; mi < 4; mi++) {
            const int r0 = bm + warpM + mi * 16 + er;
#pragma unroll
            for (int nj = 0; nj < 4; nj++) {
                const int c = bn + warpN + nj * 8 + ec;
                *(float2*)&C[(size_t)r0 * N + c]       = make_float2(acc[mi][nj][0], acc[mi][nj][1]);
                *(float2*)&C[(size_t)(r0 + 8) * N + c] = make_float2(acc[mi][nj][2], acc[mi][nj][3]);
            }
        }
    } else {
#pragma unroll
        for (int mi = 0; mi < 4; mi++) {
            const int r0 = bm + warpM + mi * 16 + er;
#pragma unroll
            for (int nj = 0; nj < 4; nj++) {
                const int c = bn + warpN + nj * 8 + ec;
                float v0 = acc[mi][nj][0], v1 = acc[mi][nj][1];
                float v2 = acc[mi][nj][2], v3 = acc[mi][nj][3];
                float h0 = __bfloat162float(__float2bfloat16_rn(v0));
                float h1 = __bfloat162float(__float2bfloat16_rn(v1));
                float h2 = __bfloat162float(__float2bfloat16_rn(v2));
                float h3 = __bfloat162float(__float2bfloat16_rn(v3));
                *(uint32_t*)&Ch[(size_t)r0 * N + c]       = packbf(h0, h1);
                *(uint32_t*)&Cl[(size_t)r0 * N + c]       = packbf(v0 - h0, v1 - h1);
                *(uint32_t*)&Ch[(size_t)(r0 + 8) * N + c] = packbf(h2, h3);
                *(uint32_t*)&Cl[(size_t)(r0 + 8) * N + c] = packbf(v2 - h2, v3 - h3);
            }
        }
    }
}

// ===========================================================================
// Flash attention, bf16x3, BK=64, 3-stage cp.async pipeline, 2 CTAs/SM.
// BQ=128 (warp = 16 rows), HD=64, 256 threads.
// ===========================================================================
#define FA_STG  32768                    // KH,KL,VH,VL each 8KB
#define FA_SMEM (NSTG * FA_STG)          // 98304 B

__global__ __launch_bounds__(256, 2) void flash_split(
    const __nv_bfloat16* __restrict__ qh_g, const __nv_bfloat16* __restrict__ ql_g,
    const float* __restrict__ head_w,
    __nv_bfloat16* __restrict__ aoh, __nv_bfloat16* __restrict__ aol)
{
    extern __shared__ char smem[];
    const uint32_t sb = smem_u32(smem);

    const int tid  = threadIdx.x;
    const int wid  = tid >> 5;
    const int lane = tid & 31;
    const int q0 = blockIdx.x * 128;
    const int h  = blockIdx.y;
    const int b  = blockIdx.z;

    float hw;
    {
        float mx = -1e30f;
#pragma unroll
        for (int i = 0; i < NHEAD; i++) mx = fmaxf(mx, head_w[i]);
        float ssum = 0.f;
#pragma unroll
        for (int i = 0; i < NHEAD; i++) ssum += __expf(head_w[i] - mx);
        hw = __expf(head_w[h] - mx) / ssum;
    }

    // ---- stage Q (hi -> [0,16K), lo -> [16K,32K)), read fragments ----
    {
        const int crow = tid >> 1;
        const int chalf = tid & 1;
        const size_t qoff = (size_t)(b * SEQ + q0 + crow) * 3 * DIMC + h * HD + chalf * 32;
#pragma unroll
        for (int j = 0; j < 4; j++) {
            uint32_t off = (uint32_t)(crow * 128 + (chalf * 4 + j) * 16);
            off = off ^ ((off >> 3) & 0x70);
            CP16(sb + off, qh_g + qoff + j * 8);
            CP16(sb + 16384 + off, ql_g + qoff + j * 8);
        }
        CP_COMMIT();
        CP_WAIT0();
        __syncthreads();
    }

    const int lrow = lane & 15;
    const int kb   = (lane >> 4) * 16;
    uint32_t qh[4][4], ql[4][4];
    {
        const uint32_t aOff = (uint32_t)((wid * 16 + lrow) * 128);
        const uint32_t aSwz = (uint32_t)((lrow & 7) << 4);
#pragma unroll
        for (int ks = 0; ks < 4; ks++) {
            const uint32_t koff = (uint32_t)(ks * 32 + kb);
            ldsm_x4(qh[ks], sb + aOff + (koff ^ aSwz));
            ldsm_x4(ql[ks], sb + 16384 + aOff + (koff ^ aSwz));
        }
    }
    __syncthreads();   // Q fully read before KV overwrites stage 0

    // KV staging geometry: row4 = tid>>2 (0..63), quarter = tid&3 (2 chunks)
    const int row4 = tid >> 2;
    const int q4   = tid & 3;
    uint32_t stK[2];
#pragma unroll
    for (int j = 0; j < 2; j++) {
        uint32_t off = (uint32_t)(row4 * 128 + (q4 * 2 + j) * 16);
        stK[j] = off ^ ((off >> 3) & 0x70);
    }
    const size_t kvbase = (size_t)(b * SEQ + row4) * 3 * DIMC + h * HD + q4 * 16;
    const size_t kstep  = (size_t)64 * 3 * DIMC;   // 64 seq rows per tile

    const int ntl = SEQ / 64;            // 32 tiles

    // prologue: issue KV tiles 0, 1
#pragma unroll
    for (int p = 0; p < NSTG - 1; p++) {
        const uint32_t s = sb + (uint32_t)p * FA_STG;
        const size_t kt_ = kvbase + (size_t)p * kstep + (size_t)1 * DIMC;
        const size_t vt_ = kvbase + (size_t)p * kstep + (size_t)2 * DIMC;
#pragma unroll
        for (int j = 0; j < 2; j++) {
            CP16(s + 0*8192 + stK[j], qh_g + kt_ + j * 8);
            CP16(s + 1*8192 + stK[j], ql_g + kt_ + j * 8);
            CP16(s + 2*8192 + stK[j], qh_g + vt_ + j * 8);
            CP16(s + 3*8192 + stK[j], ql_g + vt_ + j * 8);
        }
        CP_COMMIT();
    }

    uint32_t bOff[4];
#pragma unroll
    for (int g = 0; g < 4; g++) bOff[g] = (uint32_t)((g * 16 + lrow) * 128);
    const uint32_t bSwz = (uint32_t)((lrow & 7) << 4);
    const uint32_t vRowBase = (uint32_t)(lane & 15);
    const uint32_t vColPart = (uint32_t)((lane >> 4) * 16);

    float m_r[2] = {-1e30f, -1e30f};
    float l_r[2] = {0.f, 0.f};
    float o[8][4];
#pragma unroll
    for (int g = 0; g < 8; g++)
#pragma unroll
        for (int e = 0; e < 4; e++) o[g][e] = 0.f;

    for (int kt = 0; kt < ntl; kt++) {
        if (kt + 1 < ntl) CP_WAIT1(); else CP_WAIT0();
        __syncthreads();

        if (kt + 2 < ntl) {
            const uint32_t s = sb + (uint32_t)((kt + 2) % NSTG) * FA_STG;
            const size_t kt_ = kvbase + (size_t)(kt + 2) * kstep + (size_t)1 * DIMC;
            const size_t vt_ = kvbase + (size_t)(kt + 2) * kstep + (size_t)2 * DIMC;
#pragma unroll
            for (int j = 0; j < 2; j++) {
                CP16(s + 0*8192 + stK[j], qh_g + kt_ + j * 8);
                CP16(s + 1*8192 + stK[j], ql_g + kt_ + j * 8);
                CP16(s + 2*8192 + stK[j], qh_g + vt_ + j * 8);
                CP16(s + 3*8192 + stK[j], ql_g + vt_ + j * 8);
            }
            CP_COMMIT();
        }

        const uint32_t sKH = sb + (uint32_t)(kt % NSTG) * FA_STG;
        const uint32_t sKL = sKH + 8192;
        const uint32_t sVH = sKH + 16384;
        const uint32_t sVL = sKH + 24576;

        // ---- S = Q K^T (bf16x3): 16 q-rows x 64 keys per warp ----
        float s[8][4];
#pragma unroll
        for (int nj = 0; nj < 8; nj++)
#pragma unroll
            for (int e = 0; e < 4; e++) s[nj][e] = 0.f;

#pragma unroll
        for (int ks = 0; ks < 4; ks++) {
            const uint32_t koff = (uint32_t)(ks * 32 + kb);
#pragma unroll
            for (int g = 0; g < 4; g++) {
                uint32_t kh4[4], kl4[4];
                ldsm_x4(kh4, sKH + bOff[g] + (koff ^ bSwz));
                ldsm_x4(kl4, sKL + bOff[g] + (koff ^ bSwz));
                mma_bf16(s[2*g],   qh[ks], kh4[0], kh4[2]);
                mma_bf16(s[2*g+1], qh[ks], kh4[1], kh4[3]);
                mma_bf16(s[2*g],   qh[ks], kl4[0], kl4[2]);
                mma_bf16(s[2*g+1], qh[ks], kl4[1], kl4[3]);
                mma_bf16(s[2*g],   ql[ks], kh4[0], kh4[2]);
                mma_bf16(s[2*g+1], ql[ks], kh4[1], kh4[3]);
            }
        }

        // ---- online softmax ----
        float mx0 = -1e30f, mx1 = -1e30f;
#pragma unroll
        for (int nj = 0; nj < 8; nj++) {
            s[nj][0] *= SCALE; s[nj][1] *= SCALE; s[nj][2] *= SCALE; s[nj][3] *= SCALE;
            mx0 = fmaxf(mx0, fmaxf(s[nj][0], s[nj][1]));
            mx1 = fmaxf(mx1, fmaxf(s[nj][2], s[nj][3]));
        }
        mx0 = fmaxf(mx0, __shfl_xor_sync(0xffffffffu, mx0, 1));
        mx0 = fmaxf(mx0, __shfl_xor_sync(0xffffffffu, mx0, 2));
        mx1 = fmaxf(mx1, __shfl_xor_sync(0xffffffffu, mx1, 1));
        mx1 = fmaxf(mx1, __shfl_xor_sync(0xffffffffu, mx1, 2));
        const float mn0 = fmaxf(m_r[0], mx0);
        const float mn1 = fmaxf(m_r[1], mx1);
        const float alpha0 = __expf(m_r[0] - mn0);
        const float alpha1 = __expf(m_r[1] - mn1);
        m_r[0] = mn0; m_r[1] = mn1;
        float sum0 = 0.f, sum1 = 0.f;
#pragma unroll
        for (int nj = 0; nj < 8; nj++) {
            s[nj][0] = __expf(s[nj][0] - mn0); sum0 += s[nj][0];
            s[nj][1] = __expf(s[nj][1] - mn0); sum0 += s[nj][1];
            s[nj][2] = __expf(s[nj][2] - mn1); sum1 += s[nj][2];
            s[nj][3] = __expf(s[nj][3] - mn1); sum1 += s[nj][3];
        }
        sum0 += __shfl_xor_sync(0xffffffffu, sum0, 1);
        sum0 += __shfl_xor_sync(0xffffffffu, sum0, 2);
        sum1 += __shfl_xor_sync(0xffffffffu, sum1, 1);
        sum1 += __shfl_xor_sync(0xffffffffu, sum1, 2);
        l_r[0] = l_r[0] * alpha0 + sum0;
        l_r[1] = l_r[1] * alpha1 + sum1;
#pragma unroll
        for (int g = 0; g < 8; g++) {
            o[g][0] *= alpha0; o[g][1] *= alpha0;
            o[g][2] *= alpha1; o[g][3] *= alpha1;
        }

        // ---- O += P V (bf16x3): 4 k-steps of 16 keys ----
#pragma unroll
        for (int t = 0; t < 4; t++) {
            uint32_t pa_h[4], pa_l[4];
            {
                float e0 = s[2*t][0], e1 = s[2*t][1], e2 = s[2*t][2], e3 = s[2*t][3];
                float f0 = s[2*t+1][0], f1 = s[2*t+1][1], f2 = s[2*t+1][2], f3 = s[2*t+1][3];
                float h0 = __bfloat162float(__float2bfloat16_rn(e0));
                float h1 = __bfloat162float(__float2bfloat16_rn(e1));
                float h2 = __bfloat162float(__float2bfloat16_rn(e2));
                float h3 = __bfloat162float(__float2bfloat16_rn(e3));
                float g0 = __bfloat162float(__float2bfloat16_rn(f0));
                float g1 = __bfloat162float(__float2bfloat16_rn(f1));
                float g2 = __bfloat162float(__float2bfloat16_rn(f2));
                float g3 = __bfloat162float(__float2bfloat16_rn(f3));
                pa_h[0] = packbf(h0, h1); pa_h[1] = packbf(h2, h3);
                pa_h[2] = packbf(g0, g1); pa_h[3] = packbf(g2, g3);
                pa_l[0] = packbf(e0-h0, e1-h1); pa_l[1] = packbf(e2-h2, e3-h3);
                pa_l[2] = packbf(f0-g0, f1-g1); pa_l[3] = packbf(f2-g2, f3-g3);
            }
#pragma unroll
            for (int g = 0; g < 4; g++) {
                const uint32_t vr = (uint32_t)(16 * t) + vRowBase;
                const uint32_t vc = (uint32_t)(g * 32) + vColPart;
                const uint32_t voff = vr * 128 + (vc ^ ((vr & 7) << 4));
                uint32_t vh4[4], vl4[4];
                ldsm_x4_t(vh4, sVH + voff);
                ldsm_x4_t(vl4, sVL + voff);
                mma_bf16(o[2*g],   pa_h, vh4[0], vh4[1]);
                mma_bf16(o[2*g+1], pa_h, vh4[2], vh4[3]);
                mma_bf16(o[2*g],   pa_h, vl4[0], vl4[1]);
                mma_bf16(o[2*g+1], pa_h, vl4[2], vl4[3]);
                mma_bf16(o[2*g],   pa_l, vh4[0], vh4[1]);
                mma_bf16(o[2*g+1], pa_l, vh4[2], vh4[3]);
            }
        }
    }

    // ---- epilogue: O/l * hw -> split bf16 ao ----
    const int er = lane >> 2;
    const int ec = (lane & 3) * 2;
    const float inv0 = hw / l_r[0];
    const float inv1 = hw / l_r[1];
    const int r0 = q0 + wid * 16 + er;
#pragma unroll
    for (int g = 0; g < 8; g++) {
        const int d = h * HD + g * 8 + ec;
        float f0 = o[g][0] * inv0, f1 = o[g][1] * inv0;
        float f2 = o[g][2] * inv1, f3 = o[g][3] * inv1;
        float h0 = __bfloat162float(__float2bfloat16_rn(f0));
        float h1 = __bfloat162float(__float2bfloat16_rn(f1));
        float h2 = __bfloat162float(__float2bfloat16_rn(f2));
        float h3 = __bfloat162float(__float2bfloat16_rn(f3));
        const size_t i0 = (size_t)(b * SEQ + r0) * DIMC + d;
        const size_t i1 = (size_t)(b * SEQ + r0 + 8) * DIMC + d;
        *(uint32_t*)&aoh[i0] = packbf(h0, h1);
        *(uint32_t*)&aol[i0] = packbf(f0 - h0, f1 - h1);
        *(uint32_t*)&aoh[i1] = packbf(h2, h3);
        *(uint32_t*)&aol[i1] = packbf(f2 - h2, f3 - h3);
    }
}

// ===========================================================================
extern "C" void kernel_launch(void* const* d_in, const int* in_sizes, int n_in,
                              void* d_out, int out_size)
{
    const float* x      = (const float*)d_in[0];
    const float* w_qkv  = (const float*)d_in[1];
    const float* w_proj = (const float*)d_in[2];
    const float* head_w = (const float*)d_in[3];
    float* out = (float*)d_out;

    __nv_bfloat16 *xh, *xl, *wqh, *wql, *wph, *wpl, *qh, *ql, *aoh, *aol;
    cudaGetSymbolAddress((void**)&xh,  g_xh);  cudaGetSymbolAddress((void**)&xl,  g_xl);
    cudaGetSymbolAddress((void**)&wqh, g_wqh); cudaGetSymbolAddress((void**)&wql, g_wql);
    cudaGetSymbolAddress((void**)&wph, g_wph); cudaGetSymbolAddress((void**)&wpl, g_wpl);
    cudaGetSymbolAddress((void**)&qh,  g_qh);  cudaGetSymbolAddress((void**)&ql,  g_ql);
    cudaGetSymbolAddress((void**)&aoh, g_aoh); cudaGetSymbolAddress((void**)&aol, g_aol);

    cudaFuncSetAttribute(gemm_split, cudaFuncAttributeMaxDynamicSharedMemorySize, GEMM_SMEM);
    cudaFuncSetAttribute(flash_split, cudaFuncAttributeMaxDynamicSharedMemorySize, FA_SMEM);

    // 0) split prepass
    split32<<<(M_TOT * DIMC) / 1024, 256>>>(x, xh, xl, M_TOT * DIMC);
    split32<<<(QKV_N * DIMC) / 1024, 256>>>(w_qkv, wqh, wql, QKV_N * DIMC);
    split32<<<(DIMC * DIMC) / 1024, 256>>>(w_proj, wph, wpl, DIMC * DIMC);

    // 1) QKV projection -> split bf16 qkv
    dim3 g1(QKV_N / 128, M_TOT / 128);
    gemm_split<<<g1, 256, GEMM_SMEM>>>(xh, xl, wqh, wql, nullptr, qh, ql,
                                       M_TOT, QKV_N, DIMC);

    // 2) flash attention + head weights -> split bf16 ao
    dim3 g2(SEQ / 128, NHEAD, BATCH);
    flash_split<<<g2, 256, FA_SMEM>>>(qh, ql, head_w, aoh, aol);

    // 3) output projection -> fp32 out
    dim3 g3(DIMC / 128, M_TOT / 128);
    gemm_split<<<g3, 256, GEMM_SMEM>>>(aoh, aol, wph, wpl, out, nullptr, nullptr,
                                       M_TOT, DIMC, DIMC);
}

// round 9
// speedup vs baseline: 2.4764x; 1.0054x over previous
#include <cuda_runtime.h>
#include <cuda_bf16.h>
#include <cstdint>

#define BATCH 2
#define SEQ   2048
#define DIMC  1024
#define NHEAD 16
#define HD    64
#define SCALE 0.125f            // 64^-0.5

#define M_TOT (BATCH*SEQ)       // 4096
#define QKV_N (3*DIMC)          // 3072

// Pre-split bf16 hi/lo scratch (allocation-free rule: __device__ globals)
__device__ __nv_bfloat16 g_xh [(size_t)M_TOT * DIMC],  g_xl [(size_t)M_TOT * DIMC];
__device__ __nv_bfloat16 g_wqh[(size_t)QKV_N * DIMC],  g_wql[(size_t)QKV_N * DIMC];
__device__ __nv_bfloat16 g_wph[(size_t)DIMC * DIMC],   g_wpl[(size_t)DIMC * DIMC];
__device__ __nv_bfloat16 g_qh [(size_t)M_TOT * QKV_N], g_ql [(size_t)M_TOT * QKV_N];
__device__ __nv_bfloat16 g_aoh[(size_t)M_TOT * DIMC],  g_aol[(size_t)M_TOT * DIMC];

// ===========================================================================
// Primitives
// ===========================================================================
__device__ __forceinline__ uint32_t smem_u32(const void* p) {
    uint32_t a;
    asm("{ .reg .u64 t; cvta.to.shared.u64 t, %1; cvt.u32.u64 %0, t; }" : "=r"(a) : "l"(p));
    return a;
}
__device__ __forceinline__ void ldsm_x4(uint32_t* r, uint32_t addr) {
    asm volatile("ldmatrix.sync.aligned.m8n8.x4.shared.b16 {%0,%1,%2,%3}, [%4];"
        : "=r"(r[0]), "=r"(r[1]), "=r"(r[2]), "=r"(r[3]) : "r"(addr));
}
__device__ __forceinline__ void ldsm_x4_t(uint32_t* r, uint32_t addr) {
    asm volatile("ldmatrix.sync.aligned.m8n8.x4.trans.shared.b16 {%0,%1,%2,%3}, [%4];"
        : "=r"(r[0]), "=r"(r[1]), "=r"(r[2]), "=r"(r[3]) : "r"(addr));
}
__device__ __forceinline__ void mma_bf16(float* d, const uint32_t* a, uint32_t b0, uint32_t b1) {
    asm volatile(
        "mma.sync.aligned.m16n8k16.row.col.f32.bf16.bf16.f32 "
        "{%0,%1,%2,%3}, {%4,%5,%6,%7}, {%8,%9}, {%0,%1,%2,%3};"
        : "+f"(d[0]), "+f"(d[1]), "+f"(d[2]), "+f"(d[3])
        : "r"(a[0]), "r"(a[1]), "r"(a[2]), "r"(a[3]), "r"(b0), "r"(b1));
}
__device__ __forceinline__ uint32_t packbf(float lo, float hi) {
    __nv_bfloat162 t = __floats2bfloat162_rn(lo, hi);
    return *reinterpret_cast<uint32_t*>(&t);
}
#define CP16(dst, src) \
    asm volatile("cp.async.cg.shared.global [%0], [%1], 16;" \
        :: "r"(dst), "l"(__cvta_generic_to_global(src)) : "memory")
#define CP_COMMIT() asm volatile("cp.async.commit_group;" ::: "memory")
#define CP_WAIT0()  asm volatile("cp.async.wait_group 0;" ::: "memory")
#define CP_WAIT1()  asm volatile("cp.async.wait_group 1;" ::: "memory")

// ===========================================================================
// Split prepass: fp32 -> bf16 hi + bf16 lo
// ===========================================================================
__global__ __launch_bounds__(256) void split32(
    const float* __restrict__ in, __nv_bfloat16* __restrict__ hi,
    __nv_bfloat16* __restrict__ lo, int n)
{
    int i = (blockIdx.x * 256 + threadIdx.x) * 4;
    if (i >= n) return;
    float4 v = *(const float4*)(in + i);
    float h0 = __bfloat162float(__float2bfloat16_rn(v.x));
    float h1 = __bfloat162float(__float2bfloat16_rn(v.y));
    float h2 = __bfloat162float(__float2bfloat16_rn(v.z));
    float h3 = __bfloat162float(__float2bfloat16_rn(v.w));
    *(uint2*)(hi + i) = make_uint2(packbf(h0, h1), packbf(h2, h3));
    *(uint2*)(lo + i) = make_uint2(packbf(v.x - h0, v.y - h1), packbf(v.z - h2, v.w - h3));
}

// ===========================================================================
// bf16x3 split GEMM-NT, cp.async 3-stage pipeline, K-chunk 32, 2 CTAs/SM.
// All 12 LDSMs of a k-step hoisted before its 48 MMAs.
// ===========================================================================
#define CHK    32
#define TILE2  8192                      // 128 rows x 64 bytes
#define STG_B  (4 * TILE2)               // Ah, Al, Bh, Bl = 32KB
#define NSTG   3
#define GEMM_SMEM (NSTG * STG_B)         // 98304 B

__global__ __launch_bounds__(256, 2) void gemm_split(
    const __nv_bfloat16* __restrict__ Ah, const __nv_bfloat16* __restrict__ Al,
    const __nv_bfloat16* __restrict__ Bh, const __nv_bfloat16* __restrict__ Bl,
    float* __restrict__ C, __nv_bfloat16* __restrict__ Ch, __nv_bfloat16* __restrict__ Cl,
    int M, int N, int K)
{
    extern __shared__ char smem[];
    const uint32_t sbase = smem_u32(smem);
    const int tid  = threadIdx.x;
    const int wid  = tid >> 5;
    const int lane = tid & 31;
    const int bm = blockIdx.y * 128;
    const int bn = blockIdx.x * 128;

    const int warpM = (wid & 1) * 64;
    const int warpN = (wid >> 1) * 32;
    const int lrow = lane & 15;
    const int kb   = (lane >> 4) * 16;

    uint32_t aRow[4], aSwz[4];
#pragma unroll
    for (int mi = 0; mi < 4; mi++) {
        int r = warpM + mi * 16 + lrow;
        aRow[mi] = (uint32_t)(r * 64);
        aSwz[mi] = (uint32_t)((r & 6) << 3);
    }
    uint32_t bRow[2], bSwz[2];
#pragma unroll
    for (int nj = 0; nj < 2; nj++) {
        int r = warpN + nj * 16 + lrow;
        bRow[nj] = (uint32_t)(r * 64);
        bSwz[nj] = (uint32_t)((r & 6) << 3);
    }

    const int crow = tid >> 1;
    const int chalf = tid & 1;
    uint32_t stC[2];
#pragma unroll
    for (int j = 0; j < 2; j++) {
        uint32_t off = (uint32_t)(crow * 64 + (chalf * 2 + j) * 16);
        stC[j] = off ^ ((off >> 3) & 0x30);
    }
    const size_t aoff = (size_t)(bm + crow) * K + chalf * 16;
    const size_t boff = (size_t)(bn + crow) * K + chalf * 16;

    float acc[4][4][4];
#pragma unroll
    for (int mi = 0; mi < 4; mi++)
#pragma unroll
        for (int nj = 0; nj < 4; nj++)
#pragma unroll
            for (int k = 0; k < 4; k++) acc[mi][nj][k] = 0.f;

    const int nch = K / CHK;

#pragma unroll
    for (int p = 0; p < NSTG - 1; p++) {
        const uint32_t s = sbase + (uint32_t)p * STG_B;
        const size_t ka = aoff + (size_t)p * CHK;
        const size_t kbo = boff + (size_t)p * CHK;
#pragma unroll
        for (int j = 0; j < 2; j++) {
            CP16(s + 0*TILE2 + stC[j], Ah + ka + j * 8);
            CP16(s + 1*TILE2 + stC[j], Al + ka + j * 8);
            CP16(s + 2*TILE2 + stC[j], Bh + kbo + j * 8);
            CP16(s + 3*TILE2 + stC[j], Bl + kbo + j * 8);
        }
        CP_COMMIT();
    }

    for (int ch = 0; ch < nch; ch++) {
        if (ch + 1 < nch) CP_WAIT1(); else CP_WAIT0();
        __syncthreads();

        if (ch + 2 < nch) {
            const uint32_t s = sbase + (uint32_t)((ch + 2) % NSTG) * STG_B;
            const size_t ka = aoff + (size_t)(ch + 2) * CHK;
            const size_t kbo = boff + (size_t)(ch + 2) * CHK;
#pragma unroll
            for (int j = 0; j < 2; j++) {
                CP16(s + 0*TILE2 + stC[j], Ah + ka + j * 8);
                CP16(s + 1*TILE2 + stC[j], Al + ka + j * 8);
                CP16(s + 2*TILE2 + stC[j], Bh + kbo + j * 8);
                CP16(s + 3*TILE2 + stC[j], Bl + kbo + j * 8);
            }
            CP_COMMIT();
        }

        const uint32_t bufb = sbase + (uint32_t)(ch % NSTG) * STG_B;
#pragma unroll
        for (int ks = 0; ks < 2; ks++) {
            const uint32_t koff = (uint32_t)(ks * 32 + kb);
            uint32_t ah[4][4], al[4][4], bh[2][4], bl[2][4];
            // ---- hoist ALL 12 LDSMs: latency drains under first MMA group ----
#pragma unroll
            for (int mi = 0; mi < 4; mi++)
                ldsm_x4(ah[mi], bufb + 0*TILE2 + aRow[mi] + (koff ^ aSwz[mi]));
#pragma unroll
            for (int nj = 0; nj < 2; nj++)
                ldsm_x4(bh[nj], bufb + 2*TILE2 + bRow[nj] + (koff ^ bSwz[nj]));
#pragma unroll
            for (int nj = 0; nj < 2; nj++)
                ldsm_x4(bl[nj], bufb + 3*TILE2 + bRow[nj] + (koff ^ bSwz[nj]));
#pragma unroll
            for (int mi = 0; mi < 4; mi++)
                ldsm_x4(al[mi], bufb + 1*TILE2 + aRow[mi] + (koff ^ aSwz[mi]));
            // ---- 48 MMAs ----
#pragma unroll
            for (int mi = 0; mi < 4; mi++)
#pragma unroll
                for (int nj = 0; nj < 4; nj++)
                    mma_bf16(acc[mi][nj], ah[mi], bh[nj>>1][nj&1], bh[nj>>1][(nj&1)+2]);
#pragma unroll
            for (int mi = 0; mi < 4; mi++)
#pragma unroll
                for (int nj = 0; nj < 4; nj++)
                    mma_bf16(acc[mi][nj], ah[mi], bl[nj>>1][nj&1], bl[nj>>1][(nj&1)+2]);
#pragma unroll
            for (int mi = 0; mi < 4; mi++)
#pragma unroll
                for (int nj = 0; nj < 4; nj++)
                    mma_bf16(acc[mi][nj], al[mi], bh[nj>>1][nj&1], bh[nj>>1][(nj&1)+2]);
        }
    }

    const int er = lane >> 2;
    const int ec = (lane & 3) * 2;
    if (C) {
#pragma unroll
        for (int mi = 0; mi < 4; mi++) {
            const int r0 = bm + warpM + mi * 16 + er;
#pragma unroll
            for (int nj = 0; nj < 4; nj++) {
                const int c = bn + warpN + nj * 8 + ec;
                *(float2*)&C[(size_t)r0 * N + c]       = make_float2(acc[mi][nj][0], acc[mi][nj][1]);
                *(float2*)&C[(size_t)(r0 + 8) * N + c] = make_float2(acc[mi][nj][2], acc[mi][nj][3]);
            }
        }
    } else {
#pragma unroll
        for (int mi = 0; mi < 4; mi++) {
            const int r0 = bm + warpM + mi * 16 + er;
#pragma unroll
            for (int nj = 0; nj < 4; nj++) {
                const int c = bn + warpN + nj * 8 + ec;
                float v0 = acc[mi][nj][0], v1 = acc[mi][nj][1];
                float v2 = acc[mi][nj][2], v3 = acc[mi][nj][3];
                float h0 = __bfloat162float(__float2bfloat16_rn(v0));
                float h1 = __bfloat162float(__float2bfloat16_rn(v1));
                float h2 = __bfloat162float(__float2bfloat16_rn(v2));
                float h3 = __bfloat162float(__float2bfloat16_rn(v3));
                *(uint32_t*)&Ch[(size_t)r0 * N + c]       = packbf(h0, h1);
                *(uint32_t*)&Cl[(size_t)r0 * N + c]       = packbf(v0 - h0, v1 - h1);
                *(uint32_t*)&Ch[(size_t)(r0 + 8) * N + c] = packbf(h2, h3);
                *(uint32_t*)&Cl[(size_t)(r0 + 8) * N + c] = packbf(v2 - h2, v3 - h3);
            }
        }
    }
}

// ===========================================================================
// Flash attention, bf16x3, BK=64, 3-stage cp.async pipeline, 2 CTAs/SM.
// S-loop and PV-loop fragment loads double-buffered.
// ===========================================================================
#define FA_STG  32768                    // KH,KL,VH,VL each 8KB
#define FA_SMEM (NSTG * FA_STG)          // 98304 B

__global__ __launch_bounds__(256, 2) void flash_split(
    const __nv_bfloat16* __restrict__ qh_g, const __nv_bfloat16* __restrict__ ql_g,
    const float* __restrict__ head_w,
    __nv_bfloat16* __restrict__ aoh, __nv_bfloat16* __restrict__ aol)
{
    extern __shared__ char smem[];
    const uint32_t sb = smem_u32(smem);

    const int tid  = threadIdx.x;
    const int wid  = tid >> 5;
    const int lane = tid & 31;
    const int q0 = blockIdx.x * 128;
    const int h  = blockIdx.y;
    const int b  = blockIdx.z;

    float hw;
    {
        float mx = -1e30f;
#pragma unroll
        for (int i = 0; i < NHEAD; i++) mx = fmaxf(mx, head_w[i]);
        float ssum = 0.f;
#pragma unroll
        for (int i = 0; i < NHEAD; i++) ssum += __expf(head_w[i] - mx);
        hw = __expf(head_w[h] - mx) / ssum;
    }

    // ---- stage Q (hi -> [0,16K), lo -> [16K,32K)), read fragments ----
    {
        const int crow = tid >> 1;
        const int chalf = tid & 1;
        const size_t qoff = (size_t)(b * SEQ + q0 + crow) * 3 * DIMC + h * HD + chalf * 32;
#pragma unroll
        for (int j = 0; j < 4; j++) {
            uint32_t off = (uint32_t)(crow * 128 + (chalf * 4 + j) * 16);
            off = off ^ ((off >> 3) & 0x70);
            CP16(sb + off, qh_g + qoff + j * 8);
            CP16(sb + 16384 + off, ql_g + qoff + j * 8);
        }
        CP_COMMIT();
        CP_WAIT0();
        __syncthreads();
    }

    const int lrow = lane & 15;
    const int kb   = (lane >> 4) * 16;
    uint32_t qh[4][4], ql[4][4];
    {
        const uint32_t aOff = (uint32_t)((wid * 16 + lrow) * 128);
        const uint32_t aSwz = (uint32_t)((lrow & 7) << 4);
#pragma unroll
        for (int ks = 0; ks < 4; ks++) {
            const uint32_t koff = (uint32_t)(ks * 32 + kb);
            ldsm_x4(qh[ks], sb + aOff + (koff ^ aSwz));
            ldsm_x4(ql[ks], sb + 16384 + aOff + (koff ^ aSwz));
        }
    }
    __syncthreads();

    const int row4 = tid >> 2;
    const int q4   = tid & 3;
    uint32_t stK[2];
#pragma unroll
    for (int j = 0; j < 2; j++) {
        uint32_t off = (uint32_t)(row4 * 128 + (q4 * 2 + j) * 16);
        stK[j] = off ^ ((off >> 3) & 0x70);
    }
    const size_t kvbase = (size_t)(b * SEQ + row4) * 3 * DIMC + h * HD + q4 * 16;
    const size_t kstep  = (size_t)64 * 3 * DIMC;

    const int ntl = SEQ / 64;

#pragma unroll
    for (int p = 0; p < NSTG - 1; p++) {
        const uint32_t s = sb + (uint32_t)p * FA_STG;
        const size_t kt_ = kvbase + (size_t)p * kstep + (size_t)1 * DIMC;
        const size_t vt_ = kvbase + (size_t)p * kstep + (size_t)2 * DIMC;
#pragma unroll
        for (int j = 0; j < 2; j++) {
            CP16(s + 0*8192 + stK[j], qh_g + kt_ + j * 8);
            CP16(s + 1*8192 + stK[j], ql_g + kt_ + j * 8);
            CP16(s + 2*8192 + stK[j], qh_g + vt_ + j * 8);
            CP16(s + 3*8192 + stK[j], ql_g + vt_ + j * 8);
        }
        CP_COMMIT();
    }

    uint32_t bOff[4];
#pragma unroll
    for (int g = 0; g < 4; g++) bOff[g] = (uint32_t)((g * 16 + lrow) * 128);
    const uint32_t bSwz = (uint32_t)((lrow & 7) << 4);
    const uint32_t vRowBase = (uint32_t)(lane & 15);
    const uint32_t vColPart = (uint32_t)((lane >> 4) * 16);

    float m_r[2] = {-1e30f, -1e30f};
    float l_r[2] = {0.f, 0.f};
    float o[8][4];
#pragma unroll
    for (int g = 0; g < 8; g++)
#pragma unroll
        for (int e = 0; e < 4; e++) o[g][e] = 0.f;

    for (int kt = 0; kt < ntl; kt++) {
        if (kt + 1 < ntl) CP_WAIT1(); else CP_WAIT0();
        __syncthreads();

        if (kt + 2 < ntl) {
            const uint32_t s = sb + (uint32_t)((kt + 2) % NSTG) * FA_STG;
            const size_t kt_ = kvbase + (size_t)(kt + 2) * kstep + (size_t)1 * DIMC;
            const size_t vt_ = kvbase + (size_t)(kt + 2) * kstep + (size_t)2 * DIMC;
#pragma unroll
            for (int j = 0; j < 2; j++) {
                CP16(s + 0*8192 + stK[j], qh_g + kt_ + j * 8);
                CP16(s + 1*8192 + stK[j], ql_g + kt_ + j * 8);
                CP16(s + 2*8192 + stK[j], qh_g + vt_ + j * 8);
                CP16(s + 3*8192 + stK[j], ql_g + vt_ + j * 8);
            }
            CP_COMMIT();
        }

        const uint32_t sKH = sb + (uint32_t)(kt % NSTG) * FA_STG;
        const uint32_t sKL = sKH + 8192;
        const uint32_t sVH = sKH + 16384;
        const uint32_t sVL = sKH + 24576;

        // ---- S = Q K^T (bf16x3), double-buffered K fragments ----
        float s[8][4];
#pragma unroll
        for (int nj = 0; nj < 8; nj++)
#pragma unroll
            for (int e = 0; e < 4; e++) s[nj][e] = 0.f;

        {
            uint32_t kh4[2][4], kl4[2][4];
            ldsm_x4(kh4[0], sKH + bOff[0] + (kb ^ bSwz));
            ldsm_x4(kl4[0], sKL + bOff[0] + (kb ^ bSwz));
#pragma unroll
            for (int it = 0; it < 16; it++) {
                const int ks = it >> 2;
                const int g  = it & 3;
                const int cur = it & 1;
                if (it + 1 < 16) {
                    const int ks1 = (it + 1) >> 2;
                    const int g1  = (it + 1) & 3;
                    const uint32_t koff1 = (uint32_t)(ks1 * 32 + kb);
                    ldsm_x4(kh4[cur ^ 1], sKH + bOff[g1] + (koff1 ^ bSwz));
                    ldsm_x4(kl4[cur ^ 1], sKL + bOff[g1] + (koff1 ^ bSwz));
                }
                mma_bf16(s[2*g],   qh[ks], kh4[cur][0], kh4[cur][2]);
                mma_bf16(s[2*g+1], qh[ks], kh4[cur][1], kh4[cur][3]);
                mma_bf16(s[2*g],   qh[ks], kl4[cur][0], kl4[cur][2]);
                mma_bf16(s[2*g+1], qh[ks], kl4[cur][1], kl4[cur][3]);
                mma_bf16(s[2*g],   ql[ks], kh4[cur][0], kh4[cur][2]);
                mma_bf16(s[2*g+1], ql[ks], kh4[cur][1], kh4[cur][3]);
            }
        }

        // ---- online softmax ----
        float mx0 = -1e30f, mx1 = -1e30f;
#pragma unroll
        for (int nj = 0; nj < 8; nj++) {
            s[nj][0] *= SCALE; s[nj][1] *= SCALE; s[nj][2] *= SCALE; s[nj][3] *= SCALE;
            mx0 = fmaxf(mx0, fmaxf(s[nj][0], s[nj][1]));
            mx1 = fmaxf(mx1, fmaxf(s[nj][2], s[nj][3]));
        }
        mx0 = fmaxf(mx0, __shfl_xor_sync(0xffffffffu, mx0, 1));
        mx0 = fmaxf(mx0, __shfl_xor_sync(0xffffffffu, mx0, 2));
        mx1 = fmaxf(mx1, __shfl_xor_sync(0xffffffffu, mx1, 1));
        mx1 = fmaxf(mx1, __shfl_xor_sync(0xffffffffu, mx1, 2));
        const float mn0 = fmaxf(m_r[0], mx0);
        const float mn1 = fmaxf(m_r[1], mx1);
        const float alpha0 = __expf(m_r[0] - mn0);
        const float alpha1 = __expf(m_r[1] - mn1);
        m_r[0] = mn0; m_r[1] = mn1;
        float sum0 = 0.f, sum1 = 0.f;
#pragma unroll
        for (int nj = 0; nj < 8; nj++) {
            s[nj][0] = __expf(s[nj][0] - mn0); sum0 += s[nj][0];
            s[nj][1] = __expf(s[nj][1] - mn0); sum0 += s[nj][1];
            s[nj][2] = __expf(s[nj][2] - mn1); sum1 += s[nj][2];
            s[nj][3] = __expf(s[nj][3] - mn1); sum1 += s[nj][3];
        }
        sum0 += __shfl_xor_sync(0xffffffffu, sum0, 1);
        sum0 += __shfl_xor_sync(0xffffffffu, sum0, 2);
        sum1 += __shfl_xor_sync(0xffffffffu, sum1, 1);
        sum1 += __shfl_xor_sync(0xffffffffu, sum1, 2);
        l_r[0] = l_r[0] * alpha0 + sum0;
        l_r[1] = l_r[1] * alpha1 + sum1;
#pragma unroll
        for (int g = 0; g < 8; g++) {
            o[g][0] *= alpha0; o[g][1] *= alpha0;
            o[g][2] *= alpha1; o[g][3] *= alpha1;
        }

        // ---- precompute ALL P fragments (hi & lo) for the tile ----
        uint32_t pa_h[4][4], pa_l[4][4];
#pragma unroll
        for (int t = 0; t < 4; t++) {
            float e0 = s[2*t][0], e1 = s[2*t][1], e2 = s[2*t][2], e3 = s[2*t][3];
            float f0 = s[2*t+1][0], f1 = s[2*t+1][1], f2 = s[2*t+1][2], f3 = s[2*t+1][3];
            float h0 = __bfloat162float(__float2bfloat16_rn(e0));
            float h1 = __bfloat162float(__float2bfloat16_rn(e1));
            float h2 = __bfloat162float(__float2bfloat16_rn(e2));
            float h3 = __bfloat162float(__float2bfloat16_rn(e3));
            float g0 = __bfloat162float(__float2bfloat16_rn(f0));
            float g1 = __bfloat162float(__float2bfloat16_rn(f1));
            float g2 = __bfloat162float(__float2bfloat16_rn(f2));
            float g3 = __bfloat162float(__float2bfloat16_rn(f3));
            pa_h[t][0] = packbf(h0, h1); pa_h[t][1] = packbf(h2, h3);
            pa_h[t][2] = packbf(g0, g1); pa_h[t][3] = packbf(g2, g3);
            pa_l[t][0] = packbf(e0-h0, e1-h1); pa_l[t][1] = packbf(e2-h2, e3-h3);
            pa_l[t][2] = packbf(f0-g0, f1-g1); pa_l[t][3] = packbf(f2-g2, f3-g3);
        }

        // ---- O += P V (bf16x3), double-buffered V fragments ----
        {
            uint32_t vh4[2][4], vl4[2][4];
            {
                const uint32_t vr = vRowBase;
                const uint32_t vc = vColPart;
                const uint32_t voff = vr * 128 + (vc ^ ((vr & 7) << 4));
                ldsm_x4_t(vh4[0], sVH + voff);
                ldsm_x4_t(vl4[0], sVL + voff);
            }
#pragma unroll
            for (int it = 0; it < 16; it++) {
                const int t = it >> 2;
                const int g = it & 3;
                const int cur = it & 1;
                if (it + 1 < 16) {
                    const int t1 = (it + 1) >> 2;
                    const int g1 = (it + 1) & 3;
                    const uint32_t vr = (uint32_t)(16 * t1) + vRowBase;
                    const uint32_t vc = (uint32_t)(g1 * 32) + vColPart;
                    const uint32_t voff = vr * 128 + (vc ^ ((vr & 7) << 4));
                    ldsm_x4_t(vh4[cur ^ 1], sVH + voff);
                    ldsm_x4_t(vl4[cur ^ 1], sVL + voff);
                }
                mma_bf16(o[2*g],   pa_h[t], vh4[cur][0], vh4[cur][1]);
                mma_bf16(o[2*g+1], pa_h[t], vh4[cur][2], vh4[cur][3]);
                mma_bf16(o[2*g],   pa_h[t], vl4[cur][0], vl4[cur][1]);
                mma_bf16(o[2*g+1], pa_h[t], vl4[cur][2], vl4[cur][3]);
                mma_bf16(o[2*g],   pa_l[t], vh4[cur][0], vh4[cur][1]);
                mma_bf16(o[2*g+1], pa_l[t], vh4[cur][2], vh4[cur][3]);
            }
        }
    }

    // ---- epilogue: O/l * hw -> split bf16 ao ----
    const int er = lane >> 2;
    const int ec = (lane & 3) * 2;
    const float inv0 = hw / l_r[0];
    const float inv1 = hw / l_r[1];
    const int r0 = q0 + wid * 16 + er;
#pragma unroll
    for (int g = 0; g < 8; g++) {
        const int d = h * HD + g * 8 + ec;
        float f0 = o[g][0] * inv0, f1 = o[g][1] * inv0;
        float f2 = o[g][2] * inv1, f3 = o[g][3] * inv1;
        float h0 = __bfloat162float(__float2bfloat16_rn(f0));
        float h1 = __bfloat162float(__float2bfloat16_rn(f1));
        float h2 = __bfloat162float(__float2bfloat16_rn(f2));
        float h3 = __bfloat162float(__float2bfloat16_rn(f3));
        const size_t i0 = (size_t)(b * SEQ + r0) * DIMC + d;
        const size_t i1 = (size_t)(b * SEQ + r0 + 8) * DIMC + d;
        *(uint32_t*)&aoh[i0] = packbf(h0, h1);
        *(uint32_t*)&aol[i0] = packbf(f0 - h0, f1 - h1);
        *(uint32_t*)&aoh[i1] = packbf(h2, h3);
        *(uint32_t*)&aol[i1] = packbf(f2 - h2, f3 - h3);
    }
}

// ===========================================================================
extern "C" void kernel_launch(void* const* d_in, const int* in_sizes, int n_in,
                              void* d_out, int out_size)
{
    const float* x      = (const float*)d_in[0];
    const float* w_qkv  = (const float*)d_in[1];
    const float* w_proj = (const float*)d_in[2];
    const float* head_w = (const float*)d_in[3];
    float* out = (float*)d_out;

    __nv_bfloat16 *xh, *xl, *wqh, *wql, *wph, *wpl, *qh, *ql, *aoh, *aol;
    cudaGetSymbolAddress((void**)&xh,  g_xh);  cudaGetSymbolAddress((void**)&xl,  g_xl);
    cudaGetSymbolAddress((void**)&wqh, g_wqh); cudaGetSymbolAddress((void**)&wql, g_wql);
    cudaGetSymbolAddress((void**)&wph, g_wph); cudaGetSymbolAddress((void**)&wpl, g_wpl);
    cudaGetSymbolAddress((void**)&qh,  g_qh);  cudaGetSymbolAddress((void**)&ql,  g_ql);
    cudaGetSymbolAddress((void**)&aoh, g_aoh); cudaGetSymbolAddress((void**)&aol, g_aol);

    cudaFuncSetAttribute(gemm_split, cudaFuncAttributeMaxDynamicSharedMemorySize, GEMM_SMEM);
    cudaFuncSetAttribute(flash_split, cudaFuncAttributeMaxDynamicSharedMemorySize, FA_SMEM);

    // 0) split prepass
    split32<<<(M_TOT * DIMC) / 1024, 256>>>(x, xh, xl, M_TOT * DIMC);
    split32<<<(QKV_N * DIMC) / 1024, 256>>>(w_qkv, wqh, wql, QKV_N * DIMC);
    split32<<<(DIMC * DIMC) / 1024, 256>>>(w_proj, wph, wpl, DIMC * DIMC);

    // 1) QKV projection -> split bf16 qkv
    dim3 g1(QKV_N / 128, M_TOT / 128);
    gemm_split<<<g1, 256, GEMM_SMEM>>>(xh, xl, wqh, wql, nullptr, qh, ql,
                                       M_TOT, QKV_N, DIMC);

    // 2) flash attention + head weights -> split bf16 ao
    dim3 g2(SEQ / 128, NHEAD, BATCH);
    flash_split<<<g2, 256, FA_SMEM>>>(qh, ql, head_w, aoh, aol);

    // 3) output projection -> fp32 out
    dim3 g3(DIMC / 128, M_TOT / 128);
    gemm_split<<<g3, 256, GEMM_SMEM>>>(aoh, aol, wph, wpl, out, nullptr, nullptr,
                                       M_TOT, DIMC, DIMC);
}

// round 10
// speedup vs baseline: 5.9642x; 2.4085x over previous
#include <cuda_runtime.h>
#include <cuda_fp16.h>
#include <cstdint>

#define BATCH 2
#define SEQ   2048
#define DIMC  1024
#define NHEAD 16
#define HD    64
#define SCALE 0.125f            // 64^-0.5

#define M_TOT (BATCH*SEQ)       // 4096
#define QKV_N (3*DIMC)          // 3072

// fp16 scratch (allocation-free rule: __device__ globals)
__device__ __half g_xh [(size_t)M_TOT * DIMC];
__device__ __half g_wqh[(size_t)QKV_N * DIMC];
__device__ __half g_wph[(size_t)DIMC * DIMC];
__device__ __half g_qh [(size_t)M_TOT * QKV_N];
__device__ __half g_aoh[(size_t)M_TOT * DIMC];

// ===========================================================================
// Primitives
// ===========================================================================
__device__ __forceinline__ uint32_t smem_u32(const void* p) {
    uint32_t a;
    asm("{ .reg .u64 t; cvta.to.shared.u64 t, %1; cvt.u32.u64 %0, t; }" : "=r"(a) : "l"(p));
    return a;
}
__device__ __forceinline__ void ldsm_x4(uint32_t* r, uint32_t addr) {
    asm volatile("ldmatrix.sync.aligned.m8n8.x4.shared.b16 {%0,%1,%2,%3}, [%4];"
        : "=r"(r[0]), "=r"(r[1]), "=r"(r[2]), "=r"(r[3]) : "r"(addr));
}
__device__ __forceinline__ void ldsm_x4_t(uint32_t* r, uint32_t addr) {
    asm volatile("ldmatrix.sync.aligned.m8n8.x4.trans.shared.b16 {%0,%1,%2,%3}, [%4];"
        : "=r"(r[0]), "=r"(r[1]), "=r"(r[2]), "=r"(r[3]) : "r"(addr));
}
// D(16x8 f32) += A(16x16 f16) * B(16x8 f16, col)
__device__ __forceinline__ void mma_f16(float* d, const uint32_t* a, uint32_t b0, uint32_t b1) {
    asm volatile(
        "mma.sync.aligned.m16n8k16.row.col.f32.f16.f16.f32 "
        "{%0,%1,%2,%3}, {%4,%5,%6,%7}, {%8,%9}, {%0,%1,%2,%3};"
        : "+f"(d[0]), "+f"(d[1]), "+f"(d[2]), "+f"(d[3])
        : "r"(a[0]), "r"(a[1]), "r"(a[2]), "r"(a[3]), "r"(b0), "r"(b1));
}
__device__ __forceinline__ uint32_t packh(float lo, float hi) {
    __half2 t = __floats2half2_rn(lo, hi);
    return *reinterpret_cast<uint32_t*>(&t);
}
#define CP16(dst, src) \
    asm volatile("cp.async.cg.shared.global [%0], [%1], 16;" \
        :: "r"(dst), "l"(__cvta_generic_to_global(src)) : "memory")
#define CP_COMMIT() asm volatile("cp.async.commit_group;" ::: "memory")
#define CP_WAIT0()  asm volatile("cp.async.wait_group 0;" ::: "memory")
#define CP_WAIT1()  asm volatile("cp.async.wait_group 1;" ::: "memory")
#define CP_WAIT2()  asm volatile("cp.async.wait_group 2;" ::: "memory")

// ===========================================================================
// Convert prepass: fp32 -> fp16
// ===========================================================================
__global__ __launch_bounds__(256) void cvt16(
    const float* __restrict__ in, __half* __restrict__ out, int n)
{
    int i = (blockIdx.x * 256 + threadIdx.x) * 4;
    if (i >= n) return;
    float4 v = *(const float4*)(in + i);
    *(uint2*)(out + i) = make_uint2(packh(v.x, v.y), packh(v.z, v.w));
}

// ===========================================================================
// fp16 GEMM-NT, cp.async 4-stage pipeline, K-chunk 32, 2 CTAs/SM.
// C[M,N] = A[M,K] * B[N,K]^T, fp32 accum. Out: fp32 C or fp16 Ch.
// ===========================================================================
#define CHK    32
#define TILE2  8192                      // 128 rows x 64 bytes
#define STG_B  (2 * TILE2)               // Ah, Bh = 16KB
#define NSTG   4
#define GEMM_SMEM (NSTG * STG_B)         // 65536 B

__global__ __launch_bounds__(256, 2) void gemm_half(
    const __half* __restrict__ Ah, const __half* __restrict__ Bh,
    float* __restrict__ C, __half* __restrict__ Ch,
    int M, int N, int K)
{
    extern __shared__ char smem[];
    const uint32_t sbase = smem_u32(smem);
    const int tid  = threadIdx.x;
    const int wid  = tid >> 5;
    const int lane = tid & 31;
    const int bm = blockIdx.y * 128;
    const int bn = blockIdx.x * 128;

    const int warpM = (wid & 1) * 64;
    const int warpN = (wid >> 1) * 32;
    const int lrow = lane & 15;
    const int kb   = (lane >> 4) * 16;

    uint32_t aRow[4], aSwz[4];
#pragma unroll
    for (int mi = 0; mi < 4; mi++) {
        int r = warpM + mi * 16 + lrow;
        aRow[mi] = (uint32_t)(r * 64);
        aSwz[mi] = (uint32_t)((r & 6) << 3);
    }
    uint32_t bRow[2], bSwz[2];
#pragma unroll
    for (int nj = 0; nj < 2; nj++) {
        int r = warpN + nj * 16 + lrow;
        bRow[nj] = (uint32_t)(r * 64);
        bSwz[nj] = (uint32_t)((r & 6) << 3);
    }

    const int crow = tid >> 1;
    const int chalf = tid & 1;
    uint32_t stC[2];
#pragma unroll
    for (int j = 0; j < 2; j++) {
        uint32_t off = (uint32_t)(crow * 64 + (chalf * 2 + j) * 16);
        stC[j] = off ^ ((off >> 3) & 0x30);
    }
    const size_t aoff = (size_t)(bm + crow) * K + chalf * 16;
    const size_t boff = (size_t)(bn + crow) * K + chalf * 16;

    float acc[4][4][4];
#pragma unroll
    for (int mi = 0; mi < 4; mi++)
#pragma unroll
        for (int nj = 0; nj < 4; nj++)
#pragma unroll
            for (int k = 0; k < 4; k++) acc[mi][nj][k] = 0.f;

    const int nch = K / CHK;

#pragma unroll
    for (int p = 0; p < NSTG - 1; p++) {
        const uint32_t s = sbase + (uint32_t)p * STG_B;
        const size_t ka = aoff + (size_t)p * CHK;
        const size_t kbo = boff + (size_t)p * CHK;
#pragma unroll
        for (int j = 0; j < 2; j++) {
            CP16(s + 0*TILE2 + stC[j], Ah + ka + j * 8);
            CP16(s + 1*TILE2 + stC[j], Bh + kbo + j * 8);
        }
        CP_COMMIT();
    }

    for (int ch = 0; ch < nch; ch++) {
        const int rem = nch - 1 - ch;
        if (rem >= 2) CP_WAIT2(); else if (rem == 1) CP_WAIT1(); else CP_WAIT0();
        __syncthreads();

        if (ch + NSTG - 1 < nch) {
            const uint32_t s = sbase + (uint32_t)((ch + NSTG - 1) % NSTG) * STG_B;
            const size_t ka = aoff + (size_t)(ch + NSTG - 1) * CHK;
            const size_t kbo = boff + (size_t)(ch + NSTG - 1) * CHK;
#pragma unroll
            for (int j = 0; j < 2; j++) {
                CP16(s + 0*TILE2 + stC[j], Ah + ka + j * 8);
                CP16(s + 1*TILE2 + stC[j], Bh + kbo + j * 8);
            }
            CP_COMMIT();
        }

        const uint32_t bufb = sbase + (uint32_t)(ch % NSTG) * STG_B;
#pragma unroll
        for (int ks = 0; ks < 2; ks++) {
            const uint32_t koff = (uint32_t)(ks * 32 + kb);
            uint32_t ah[4][4], bh[2][4];
#pragma unroll
            for (int mi = 0; mi < 4; mi++)
                ldsm_x4(ah[mi], bufb + 0*TILE2 + aRow[mi] + (koff ^ aSwz[mi]));
#pragma unroll
            for (int nj = 0; nj < 2; nj++)
                ldsm_x4(bh[nj], bufb + 1*TILE2 + bRow[nj] + (koff ^ bSwz[nj]));
#pragma unroll
            for (int mi = 0; mi < 4; mi++)
#pragma unroll
                for (int nj = 0; nj < 4; nj++)
                    mma_f16(acc[mi][nj], ah[mi], bh[nj>>1][nj&1], bh[nj>>1][(nj&1)+2]);
        }
    }

    const int er = lane >> 2;
    const int ec = (lane & 3) * 2;
    if (C) {
#pragma unroll
        for (int mi = 0; mi < 4; mi++) {
            const int r0 = bm + warpM + mi * 16 + er;
#pragma unroll
            for (int nj = 0; nj < 4; nj++) {
                const int c = bn + warpN + nj * 8 + ec;
                *(float2*)&C[(size_t)r0 * N + c]       = make_float2(acc[mi][nj][0], acc[mi][nj][1]);
                *(float2*)&C[(size_t)(r0 + 8) * N + c] = make_float2(acc[mi][nj][2], acc[mi][nj][3]);
            }
        }
    } else {
#pragma unroll
        for (int mi = 0; mi < 4; mi++) {
            const int r0 = bm + warpM + mi * 16 + er;
#pragma unroll
            for (int nj = 0; nj < 4; nj++) {
                const int c = bn + warpN + nj * 8 + ec;
                *(uint32_t*)&Ch[(size_t)r0 * N + c]       = packh(acc[mi][nj][0], acc[mi][nj][1]);
                *(uint32_t*)&Ch[(size_t)(r0 + 8) * N + c] = packh(acc[mi][nj][2], acc[mi][nj][3]);
            }
        }
    }
}

// ===========================================================================
// fp16 flash attention, BK=64, 4-stage cp.async pipeline, 2 CTAs/SM.
// BQ=128 (warp = 16 rows), HD=64, 256 threads.
// ===========================================================================
#define FA_STG  16384                    // KH 8KB + VH 8KB
#define FA_SMEM (NSTG * FA_STG)          // 65536 B

__global__ __launch_bounds__(256, 2) void flash_half(
    const __half* __restrict__ qh_g, const float* __restrict__ head_w,
    __half* __restrict__ aoh)
{
    extern __shared__ char smem[];
    const uint32_t sb = smem_u32(smem);

    const int tid  = threadIdx.x;
    const int wid  = tid >> 5;
    const int lane = tid & 31;
    const int q0 = blockIdx.x * 128;
    const int h  = blockIdx.y;
    const int b  = blockIdx.z;

    float hw;
    {
        float mx = -1e30f;
#pragma unroll
        for (int i = 0; i < NHEAD; i++) mx = fmaxf(mx, head_w[i]);
        float ssum = 0.f;
#pragma unroll
        for (int i = 0; i < NHEAD; i++) ssum += __expf(head_w[i] - mx);
        hw = __expf(head_w[h] - mx) / ssum;
    }

    // ---- stage Q (fp16, 16KB) into stage 0+1 area, read fragments ----
    {
        const int crow = tid >> 1;
        const int chalf = tid & 1;
        const size_t qoff = (size_t)(b * SEQ + q0 + crow) * 3 * DIMC + h * HD + chalf * 32;
#pragma unroll
        for (int j = 0; j < 4; j++) {
            uint32_t off = (uint32_t)(crow * 128 + (chalf * 4 + j) * 16);
            off = off ^ ((off >> 3) & 0x70);
            CP16(sb + off, qh_g + qoff + j * 8);
        }
        CP_COMMIT();
        CP_WAIT0();
        __syncthreads();
    }

    const int lrow = lane & 15;
    const int kb   = (lane >> 4) * 16;
    uint32_t qh[4][4];
    {
        const uint32_t aOff = (uint32_t)((wid * 16 + lrow) * 128);
        const uint32_t aSwz = (uint32_t)((lrow & 7) << 4);
#pragma unroll
        for (int ks = 0; ks < 4; ks++) {
            const uint32_t koff = (uint32_t)(ks * 32 + kb);
            ldsm_x4(qh[ks], sb + aOff + (koff ^ aSwz));
        }
    }
    __syncthreads();   // Q fully read before KV staging overwrites

    const int row4 = tid >> 2;
    const int q4   = tid & 3;
    uint32_t stK[2];
#pragma unroll
    for (int j = 0; j < 2; j++) {
        uint32_t off = (uint32_t)(row4 * 128 + (q4 * 2 + j) * 16);
        stK[j] = off ^ ((off >> 3) & 0x70);
    }
    const size_t kvbase = (size_t)(b * SEQ + row4) * 3 * DIMC + h * HD + q4 * 16;
    const size_t kstep  = (size_t)64 * 3 * DIMC;

    const int ntl = SEQ / 64;

#pragma unroll
    for (int p = 0; p < NSTG - 1; p++) {
        const uint32_t s = sb + (uint32_t)p * FA_STG;
        const size_t kt_ = kvbase + (size_t)p * kstep + (size_t)1 * DIMC;
        const size_t vt_ = kvbase + (size_t)p * kstep + (size_t)2 * DIMC;
#pragma unroll
        for (int j = 0; j < 2; j++) {
            CP16(s + 0*8192 + stK[j], qh_g + kt_ + j * 8);
            CP16(s + 1*8192 + stK[j], qh_g + vt_ + j * 8);
        }
        CP_COMMIT();
    }

    uint32_t bOff[4];
#pragma unroll
    for (int g = 0; g < 4; g++) bOff[g] = (uint32_t)((g * 16 + lrow) * 128);
    const uint32_t bSwz = (uint32_t)((lrow & 7) << 4);
    const uint32_t vRowBase = (uint32_t)(lane & 15);
    const uint32_t vColPart = (uint32_t)((lane >> 4) * 16);

    float m_r[2] = {-1e30f, -1e30f};
    float l_r[2] = {0.f, 0.f};
    float o[8][4];
#pragma unroll
    for (int g = 0; g < 8; g++)
#pragma unroll
        for (int e = 0; e < 4; e++) o[g][e] = 0.f;

    for (int kt = 0; kt < ntl; kt++) {
        const int rem = ntl - 1 - kt;
        if (rem >= 2) CP_WAIT2(); else if (rem == 1) CP_WAIT1(); else CP_WAIT0();
        __syncthreads();

        if (kt + NSTG - 1 < ntl) {
            const uint32_t s = sb + (uint32_t)((kt + NSTG - 1) % NSTG) * FA_STG;
            const size_t kt_ = kvbase + (size_t)(kt + NSTG - 1) * kstep + (size_t)1 * DIMC;
            const size_t vt_ = kvbase + (size_t)(kt + NSTG - 1) * kstep + (size_t)2 * DIMC;
#pragma unroll
            for (int j = 0; j < 2; j++) {
                CP16(s + 0*8192 + stK[j], qh_g + kt_ + j * 8);
                CP16(s + 1*8192 + stK[j], qh_g + vt_ + j * 8);
            }
            CP_COMMIT();
        }

        const uint32_t sKH = sb + (uint32_t)(kt % NSTG) * FA_STG;
        const uint32_t sVH = sKH + 8192;

        // ---- S = Q K^T (fp16): 16 q-rows x 64 keys per warp ----
        float s[8][4];
#pragma unroll
        for (int nj = 0; nj < 8; nj++)
#pragma unroll
            for (int e = 0; e < 4; e++) s[nj][e] = 0.f;

#pragma unroll
        for (int ks = 0; ks < 4; ks++) {
            const uint32_t koff = (uint32_t)(ks * 32 + kb);
#pragma unroll
            for (int g = 0; g < 4; g++) {
                uint32_t kh4[4];
                ldsm_x4(kh4, sKH + bOff[g] + (koff ^ bSwz));
                mma_f16(s[2*g],   qh[ks], kh4[0], kh4[2]);
                mma_f16(s[2*g+1], qh[ks], kh4[1], kh4[3]);
            }
        }

        // ---- online softmax ----
        float mx0 = -1e30f, mx1 = -1e30f;
#pragma unroll
        for (int nj = 0; nj < 8; nj++) {
            s[nj][0] *= SCALE; s[nj][1] *= SCALE; s[nj][2] *= SCALE; s[nj][3] *= SCALE;
            mx0 = fmaxf(mx0, fmaxf(s[nj][0], s[nj][1]));
            mx1 = fmaxf(mx1, fmaxf(s[nj][2], s[nj][3]));
        }
        mx0 = fmaxf(mx0, __shfl_xor_sync(0xffffffffu, mx0, 1));
        mx0 = fmaxf(mx0, __shfl_xor_sync(0xffffffffu, mx0, 2));
        mx1 = fmaxf(mx1, __shfl_xor_sync(0xffffffffu, mx1, 1));
        mx1 = fmaxf(mx1, __shfl_xor_sync(0xffffffffu, mx1, 2));
        const float mn0 = fmaxf(m_r[0], mx0);
        const float mn1 = fmaxf(m_r[1], mx1);
        const float alpha0 = __expf(m_r[0] - mn0);
        const float alpha1 = __expf(m_r[1] - mn1);
        m_r[0] = mn0; m_r[1] = mn1;
        float sum0 = 0.f, sum1 = 0.f;
#pragma unroll
        for (int nj = 0; nj < 8; nj++) {
            s[nj][0] = __expf(s[nj][0] - mn0); sum0 += s[nj][0];
            s[nj][1] = __expf(s[nj][1] - mn0); sum0 += s[nj][1];
            s[nj][2] = __expf(s[nj][2] - mn1); sum1 += s[nj][2];
            s[nj][3] = __expf(s[nj][3] - mn1); sum1 += s[nj][3];
        }
        sum0 += __shfl_xor_sync(0xffffffffu, sum0, 1);
        sum0 += __shfl_xor_sync(0xffffffffu, sum0, 2);
        sum1 += __shfl_xor_sync(0xffffffffu, sum1, 1);
        sum1 += __shfl_xor_sync(0xffffffffu, sum1, 2);
        l_r[0] = l_r[0] * alpha0 + sum0;
        l_r[1] = l_r[1] * alpha1 + sum1;
#pragma unroll
        for (int g = 0; g < 8; g++) {
            o[g][0] *= alpha0; o[g][1] *= alpha0;
            o[g][2] *= alpha1; o[g][3] *= alpha1;
        }

        // ---- P fragments (fp16) ----
        uint32_t pa[4][4];
#pragma unroll
        for (int t = 0; t < 4; t++) {
            pa[t][0] = packh(s[2*t][0], s[2*t][1]);
            pa[t][1] = packh(s[2*t][2], s[2*t][3]);
            pa[t][2] = packh(s[2*t+1][0], s[2*t+1][1]);
            pa[t][3] = packh(s[2*t+1][2], s[2*t+1][3]);
        }

        // ---- O += P V (fp16) ----
#pragma unroll
        for (int t = 0; t < 4; t++) {
#pragma unroll
            for (int g = 0; g < 4; g++) {
                const uint32_t vr = (uint32_t)(16 * t) + vRowBase;
                const uint32_t vc = (uint32_t)(g * 32) + vColPart;
                const uint32_t voff = vr * 128 + (vc ^ ((vr & 7) << 4));
                uint32_t vh4[4];
                ldsm_x4_t(vh4, sVH + voff);
                mma_f16(o[2*g],   pa[t], vh4[0], vh4[1]);
                mma_f16(o[2*g+1], pa[t], vh4[2], vh4[3]);
            }
        }
    }

    // ---- epilogue: O/l * hw -> fp16 ao ----
    const int er = lane >> 2;
    const int ec = (lane & 3) * 2;
    const float inv0 = hw / l_r[0];
    const float inv1 = hw / l_r[1];
    const int r0 = q0 + wid * 16 + er;
#pragma unroll
    for (int g = 0; g < 8; g++) {
        const int d = h * HD + g * 8 + ec;
        const size_t i0 = (size_t)(b * SEQ + r0) * DIMC + d;
        const size_t i1 = (size_t)(b * SEQ + r0 + 8) * DIMC + d;
        *(uint32_t*)&aoh[i0] = packh(o[g][0] * inv0, o[g][1] * inv0);
        *(uint32_t*)&aoh[i1] = packh(o[g][2] * inv1, o[g][3] * inv1);
    }
}

// ===========================================================================
extern "C" void kernel_launch(void* const* d_in, const int* in_sizes, int n_in,
                              void* d_out, int out_size)
{
    const float* x      = (const float*)d_in[0];
    const float* w_qkv  = (const float*)d_in[1];
    const float* w_proj = (const float*)d_in[2];
    const float* head_w = (const float*)d_in[3];
    float* out = (float*)d_out;

    __half *xh, *wqh, *wph, *qh, *aoh;
    cudaGetSymbolAddress((void**)&xh,  g_xh);
    cudaGetSymbolAddress((void**)&wqh, g_wqh);
    cudaGetSymbolAddress((void**)&wph, g_wph);
    cudaGetSymbolAddress((void**)&qh,  g_qh);
    cudaGetSymbolAddress((void**)&aoh, g_aoh);

    cudaFuncSetAttribute(gemm_half, cudaFuncAttributeMaxDynamicSharedMemorySize, GEMM_SMEM);
    cudaFuncSetAttribute(flash_half, cudaFuncAttributeMaxDynamicSharedMemorySize, FA_SMEM);

    // 0) convert prepass
    cvt16<<<(M_TOT * DIMC) / 1024, 256>>>(x, xh, M_TOT * DIMC);
    cvt16<<<(QKV_N * DIMC) / 1024, 256>>>(w_qkv, wqh, QKV_N * DIMC);
    cvt16<<<(DIMC * DIMC) / 1024, 256>>>(w_proj, wph, DIMC * DIMC);

    // 1) QKV projection -> fp16 qkv
    dim3 g1(QKV_N / 128, M_TOT / 128);
    gemm_half<<<g1, 256, GEMM_SMEM>>>(xh, wqh, nullptr, qh, M_TOT, QKV_N, DIMC);

    // 2) flash attention + head weights -> fp16 ao
    dim3 g2(SEQ / 128, NHEAD, BATCH);
    flash_half<<<g2, 256, FA_SMEM>>>(qh, head_w, aoh);

    // 3) output projection -> fp32 out
    dim3 g3(DIMC / 128, M_TOT / 128);
    gemm_half<<<g3, 256, GEMM_SMEM>>>(aoh, wph, out, nullptr, M_TOT, DIMC, DIMC);
}

// round 11
// speedup vs baseline: 6.0160x; 1.0087x over previous
#include <cuda_runtime.h>
#include <cuda_fp16.h>
#include <cstdint>

#define BATCH 2
#define SEQ   2048
#define DIMC  1024
#define NHEAD 16
#define HD    64
#define SCALE 0.125f            // 64^-0.5

#define M_TOT (BATCH*SEQ)       // 4096
#define QKV_N (3*DIMC)          // 3072

// fp16 scratch (allocation-free rule: __device__ globals)
__device__ __half g_xh [(size_t)M_TOT * DIMC];
__device__ __half g_wqh[(size_t)QKV_N * DIMC];
__device__ __half g_wph[(size_t)DIMC * DIMC];
__device__ __half g_qh [(size_t)M_TOT * QKV_N];
__device__ __half g_aoh[(size_t)M_TOT * DIMC];

// ===========================================================================
// Primitives
// ===========================================================================
__device__ __forceinline__ uint32_t smem_u32(const void* p) {
    uint32_t a;
    asm("{ .reg .u64 t; cvta.to.shared.u64 t, %1; cvt.u32.u64 %0, t; }" : "=r"(a) : "l"(p));
    return a;
}
__device__ __forceinline__ void ldsm_x4(uint32_t* r, uint32_t addr) {
    asm volatile("ldmatrix.sync.aligned.m8n8.x4.shared.b16 {%0,%1,%2,%3}, [%4];"
        : "=r"(r[0]), "=r"(r[1]), "=r"(r[2]), "=r"(r[3]) : "r"(addr));
}
__device__ __forceinline__ void ldsm_x4_t(uint32_t* r, uint32_t addr) {
    asm volatile("ldmatrix.sync.aligned.m8n8.x4.trans.shared.b16 {%0,%1,%2,%3}, [%4];"
        : "=r"(r[0]), "=r"(r[1]), "=r"(r[2]), "=r"(r[3]) : "r"(addr));
}
// D(16x8 f32) += A(16x16 f16) * B(16x8 f16, col)
__device__ __forceinline__ void mma_f16(float* d, const uint32_t* a, uint32_t b0, uint32_t b1) {
    asm volatile(
        "mma.sync.aligned.m16n8k16.row.col.f32.f16.f16.f32 "
        "{%0,%1,%2,%3}, {%4,%5,%6,%7}, {%8,%9}, {%0,%1,%2,%3};"
        : "+f"(d[0]), "+f"(d[1]), "+f"(d[2]), "+f"(d[3])
        : "r"(a[0]), "r"(a[1]), "r"(a[2]), "r"(a[3]), "r"(b0), "r"(b1));
}
__device__ __forceinline__ uint32_t packh(float lo, float hi) {
    __half2 t = __floats2half2_rn(lo, hi);
    return *reinterpret_cast<uint32_t*>(&t);
}
#define CP16(dst, src) \
    asm volatile("cp.async.cg.shared.global [%0], [%1], 16;" \
        :: "r"(dst), "l"(__cvta_generic_to_global(src)) : "memory")
#define CP_COMMIT() asm volatile("cp.async.commit_group;" ::: "memory")
#define CP_WAIT0()  asm volatile("cp.async.wait_group 0;" ::: "memory")
#define CP_WAIT1()  asm volatile("cp.async.wait_group 1;" ::: "memory")
#define CP_WAIT2()  asm volatile("cp.async.wait_group 2;" ::: "memory")

// ===========================================================================
// Fused convert prepass: fp32 -> fp16 over 3 segments (one launch)
// ===========================================================================
__global__ __launch_bounds__(256) void cvt16_all(
    const float* __restrict__ x,  __half* __restrict__ xh,
    const float* __restrict__ wq, __half* __restrict__ wqh,
    const float* __restrict__ wp, __half* __restrict__ wph)
{
    const float* in;  __half* out;  int n;
    if (blockIdx.y == 0)      { in = x;  out = xh;  n = M_TOT * DIMC; }
    else if (blockIdx.y == 1) { in = wq; out = wqh; n = QKV_N * DIMC; }
    else                      { in = wp; out = wph; n = DIMC * DIMC; }
    int i = (blockIdx.x * 256 + threadIdx.x) * 4;
    if (i >= n) return;
    float4 v = *(const float4*)(in + i);
    *(uint2*)(out + i) = make_uint2(packh(v.x, v.y), packh(v.z, v.w));
}

// ===========================================================================
// fp16 GEMM-NT, cp.async 3-stage pipeline, K-chunk 64, 2 CTAs/SM.
// C[M,N] = A[M,K] * B[N,K]^T, fp32 accum. Out: fp32 C or fp16 Ch.
// 128B smem rows, SW128 swizzle (proven R5/R7 geometry).
// ===========================================================================
#define CHK    64
#define TILEK  16384                     // 128 rows x 128 bytes
#define STG_B  (2 * TILEK)               // A, B = 32KB
#define NSTG   3
#define GEMM_SMEM (NSTG * STG_B)         // 98304 B

__global__ __launch_bounds__(256, 2) void gemm_half(
    const __half* __restrict__ Ah, const __half* __restrict__ Bh,
    float* __restrict__ C, __half* __restrict__ Ch,
    int M, int N, int K)
{
    extern __shared__ char smem[];
    const uint32_t sbase = smem_u32(smem);
    const int tid  = threadIdx.x;
    const int wid  = tid >> 5;
    const int lane = tid & 31;
    const int bm = blockIdx.y * 128;
    const int bn = blockIdx.x * 128;

    const int warpM = (wid & 1) * 64;
    const int warpN = (wid >> 1) * 32;
    const int lrow = lane & 15;
    const int kb   = (lane >> 4) * 16;

    uint32_t aRow[4], aSwz[4];
#pragma unroll
    for (int mi = 0; mi < 4; mi++) {
        int r = warpM + mi * 16 + lrow;
        aRow[mi] = (uint32_t)(r * 128);
        aSwz[mi] = (uint32_t)((r & 7) << 4);
    }
    uint32_t bRow[2], bSwz[2];
#pragma unroll
    for (int nj = 0; nj < 2; nj++) {
        int r = warpN + nj * 16 + lrow;
        bRow[nj] = (uint32_t)(r * 128);
        bSwz[nj] = (uint32_t)((r & 7) << 4);
    }

    // staging: thread -> row tid>>1, half (tid&1): 4 16B chunks per tile
    const int crow = tid >> 1;
    const int chalf = tid & 1;
    uint32_t stC[4];
#pragma unroll
    for (int j = 0; j < 4; j++) {
        uint32_t off = (uint32_t)(crow * 128 + (chalf * 4 + j) * 16);
        stC[j] = off ^ ((off >> 3) & 0x70);
    }
    const size_t aoff = (size_t)(bm + crow) * K + chalf * 32;
    const size_t boff = (size_t)(bn + crow) * K + chalf * 32;

    float acc[4][4][4];
#pragma unroll
    for (int mi = 0; mi < 4; mi++)
#pragma unroll
        for (int nj = 0; nj < 4; nj++)
#pragma unroll
            for (int k = 0; k < 4; k++) acc[mi][nj][k] = 0.f;

    const int nch = K / CHK;             // 16 for K=1024

#pragma unroll
    for (int p = 0; p < NSTG - 1; p++) {
        const uint32_t s = sbase + (uint32_t)p * STG_B;
        const size_t ka = aoff + (size_t)p * CHK;
        const size_t kbo = boff + (size_t)p * CHK;
#pragma unroll
        for (int j = 0; j < 4; j++) {
            CP16(s + 0*TILEK + stC[j], Ah + ka + j * 8);
            CP16(s + 1*TILEK + stC[j], Bh + kbo + j * 8);
        }
        CP_COMMIT();
    }

    for (int ch = 0; ch < nch; ch++) {
        if (ch + 1 < nch) CP_WAIT1(); else CP_WAIT0();
        __syncthreads();

        if (ch + 2 < nch) {
            const uint32_t s = sbase + (uint32_t)((ch + 2) % NSTG) * STG_B;
            const size_t ka = aoff + (size_t)(ch + 2) * CHK;
            const size_t kbo = boff + (size_t)(ch + 2) * CHK;
#pragma unroll
            for (int j = 0; j < 4; j++) {
                CP16(s + 0*TILEK + stC[j], Ah + ka + j * 8);
                CP16(s + 1*TILEK + stC[j], Bh + kbo + j * 8);
            }
            CP_COMMIT();
        }

        const uint32_t bufb = sbase + (uint32_t)(ch % NSTG) * STG_B;
#pragma unroll
        for (int ks = 0; ks < 4; ks++) {
            const uint32_t koff = (uint32_t)(ks * 32 + kb);
            uint32_t ah[4][4], bh[2][4];
#pragma unroll
            for (int mi = 0; mi < 4; mi++)
                ldsm_x4(ah[mi], bufb + 0*TILEK + aRow[mi] + (koff ^ aSwz[mi]));
#pragma unroll
            for (int nj = 0; nj < 2; nj++)
                ldsm_x4(bh[nj], bufb + 1*TILEK + bRow[nj] + (koff ^ bSwz[nj]));
#pragma unroll
            for (int mi = 0; mi < 4; mi++)
#pragma unroll
                for (int nj = 0; nj < 4; nj++)
                    mma_f16(acc[mi][nj], ah[mi], bh[nj>>1][nj&1], bh[nj>>1][(nj&1)+2]);
        }
    }

    const int er = lane >> 2;
    const int ec = (lane & 3) * 2;
    if (C) {
#pragma unroll
        for (int mi = 0; mi < 4; mi++) {
            const int r0 = bm + warpM + mi * 16 + er;
#pragma unroll
            for (int nj = 0; nj < 4; nj++) {
                const int c = bn + warpN + nj * 8 + ec;
                *(float2*)&C[(size_t)r0 * N + c]       = make_float2(acc[mi][nj][0], acc[mi][nj][1]);
                *(float2*)&C[(size_t)(r0 + 8) * N + c] = make_float2(acc[mi][nj][2], acc[mi][nj][3]);
            }
        }
    } else {
#pragma unroll
        for (int mi = 0; mi < 4; mi++) {
            const int r0 = bm + warpM + mi * 16 + er;
#pragma unroll
            for (int nj = 0; nj < 4; nj++) {
                const int c = bn + warpN + nj * 8 + ec;
                *(uint32_t*)&Ch[(size_t)r0 * N + c]       = packh(acc[mi][nj][0], acc[mi][nj][1]);
                *(uint32_t*)&Ch[(size_t)(r0 + 8) * N + c] = packh(acc[mi][nj][2], acc[mi][nj][3]);
            }
        }
    }
}

// ===========================================================================
// fp16 flash attention, BK=64, 4-stage cp.async pipeline, 2 CTAs/SM.
// (unchanged from R10 passing kernel — near its HMMA floor)
// ===========================================================================
#define FA_NSTG 4
#define FA_STG  16384                    // KH 8KB + VH 8KB
#define FA_SMEM (FA_NSTG * FA_STG)       // 65536 B

__global__ __launch_bounds__(256, 2) void flash_half(
    const __half* __restrict__ qh_g, const float* __restrict__ head_w,
    __half* __restrict__ aoh)
{
    extern __shared__ char smem[];
    const uint32_t sb = smem_u32(smem);

    const int tid  = threadIdx.x;
    const int wid  = tid >> 5;
    const int lane = tid & 31;
    const int q0 = blockIdx.x * 128;
    const int h  = blockIdx.y;
    const int b  = blockIdx.z;

    float hw;
    {
        float mx = -1e30f;
#pragma unroll
        for (int i = 0; i < NHEAD; i++) mx = fmaxf(mx, head_w[i]);
        float ssum = 0.f;
#pragma unroll
        for (int i = 0; i < NHEAD; i++) ssum += __expf(head_w[i] - mx);
        hw = __expf(head_w[h] - mx) / ssum;
    }

    // ---- stage Q (fp16, 16KB), read fragments ----
    {
        const int crow = tid >> 1;
        const int chalf = tid & 1;
        const size_t qoff = (size_t)(b * SEQ + q0 + crow) * 3 * DIMC + h * HD + chalf * 32;
#pragma unroll
        for (int j = 0; j < 4; j++) {
            uint32_t off = (uint32_t)(crow * 128 + (chalf * 4 + j) * 16);
            off = off ^ ((off >> 3) & 0x70);
            CP16(sb + off, qh_g + qoff + j * 8);
        }
        CP_COMMIT();
        CP_WAIT0();
        __syncthreads();
    }

    const int lrow = lane & 15;
    const int kb   = (lane >> 4) * 16;
    uint32_t qh[4][4];
    {
        const uint32_t aOff = (uint32_t)((wid * 16 + lrow) * 128);
        const uint32_t aSwz = (uint32_t)((lrow & 7) << 4);
#pragma unroll
        for (int ks = 0; ks < 4; ks++) {
            const uint32_t koff = (uint32_t)(ks * 32 + kb);
            ldsm_x4(qh[ks], sb + aOff + (koff ^ aSwz));
        }
    }
    __syncthreads();   // Q fully read before KV staging overwrites

    const int row4 = tid >> 2;
    const int q4   = tid & 3;
    uint32_t stK[2];
#pragma unroll
    for (int j = 0; j < 2; j++) {
        uint32_t off = (uint32_t)(row4 * 128 + (q4 * 2 + j) * 16);
        stK[j] = off ^ ((off >> 3) & 0x70);
    }
    const size_t kvbase = (size_t)(b * SEQ + row4) * 3 * DIMC + h * HD + q4 * 16;
    const size_t kstep  = (size_t)64 * 3 * DIMC;

    const int ntl = SEQ / 64;

#pragma unroll
    for (int p = 0; p < FA_NSTG - 1; p++) {
        const uint32_t s = sb + (uint32_t)p * FA_STG;
        const size_t kt_ = kvbase + (size_t)p * kstep + (size_t)1 * DIMC;
        const size_t vt_ = kvbase + (size_t)p * kstep + (size_t)2 * DIMC;
#pragma unroll
        for (int j = 0; j < 2; j++) {
            CP16(s + 0*8192 + stK[j], qh_g + kt_ + j * 8);
            CP16(s + 1*8192 + stK[j], qh_g + vt_ + j * 8);
        }
        CP_COMMIT();
    }

    uint32_t bOff[4];
#pragma unroll
    for (int g = 0; g < 4; g++) bOff[g] = (uint32_t)((g * 16 + lrow) * 128);
    const uint32_t bSwz = (uint32_t)((lrow & 7) << 4);
    const uint32_t vRowBase = (uint32_t)(lane & 15);
    const uint32_t vColPart = (uint32_t)((lane >> 4) * 16);

    float m_r[2] = {-1e30f, -1e30f};
    float l_r[2] = {0.f, 0.f};
    float o[8][4];
#pragma unroll
    for (int g = 0; g < 8; g++)
#pragma unroll
        for (int e = 0; e < 4; e++) o[g][e] = 0.f;

    for (int kt = 0; kt < ntl; kt++) {
        const int rem = ntl - 1 - kt;
        if (rem >= 2) CP_WAIT2(); else if (rem == 1) CP_WAIT1(); else CP_WAIT0();
        __syncthreads();

        if (kt + FA_NSTG - 1 < ntl) {
            const uint32_t s = sb + (uint32_t)((kt + FA_NSTG - 1) % FA_NSTG) * FA_STG;
            const size_t kt_ = kvbase + (size_t)(kt + FA_NSTG - 1) * kstep + (size_t)1 * DIMC;
            const size_t vt_ = kvbase + (size_t)(kt + FA_NSTG - 1) * kstep + (size_t)2 * DIMC;
#pragma unroll
            for (int j = 0; j < 2; j++) {
                CP16(s + 0*8192 + stK[j], qh_g + kt_ + j * 8);
                CP16(s + 1*8192 + stK[j], qh_g + vt_ + j * 8);
            }
            CP_COMMIT();
        }

        const uint32_t sKH = sb + (uint32_t)(kt % FA_NSTG) * FA_STG;
        const uint32_t sVH = sKH + 8192;

        // ---- S = Q K^T (fp16) ----
        float s[8][4];
#pragma unroll
        for (int nj = 0; nj < 8; nj++)
#pragma unroll
            for (int e = 0; e < 4; e++) s[nj][e] = 0.f;

#pragma unroll
        for (int ks = 0; ks < 4; ks++) {
            const uint32_t koff = (uint32_t)(ks * 32 + kb);
#pragma unroll
            for (int g = 0; g < 4; g++) {
                uint32_t kh4[4];
                ldsm_x4(kh4, sKH + bOff[g] + (koff ^ bSwz));
                mma_f16(s[2*g],   qh[ks], kh4[0], kh4[2]);
                mma_f16(s[2*g+1], qh[ks], kh4[1], kh4[3]);
            }
        }

        // ---- online softmax ----
        float mx0 = -1e30f, mx1 = -1e30f;
#pragma unroll
        for (int nj = 0; nj < 8; nj++) {
            s[nj][0] *= SCALE; s[nj][1] *= SCALE; s[nj][2] *= SCALE; s[nj][3] *= SCALE;
            mx0 = fmaxf(mx0, fmaxf(s[nj][0], s[nj][1]));
            mx1 = fmaxf(mx1, fmaxf(s[nj][2], s[nj][3]));
        }
        mx0 = fmaxf(mx0, __shfl_xor_sync(0xffffffffu, mx0, 1));
        mx0 = fmaxf(mx0, __shfl_xor_sync(0xffffffffu, mx0, 2));
        mx1 = fmaxf(mx1, __shfl_xor_sync(0xffffffffu, mx1, 1));
        mx1 = fmaxf(mx1, __shfl_xor_sync(0xffffffffu, mx1, 2));
        const float mn0 = fmaxf(m_r[0], mx0);
        const float mn1 = fmaxf(m_r[1], mx1);
        const float alpha0 = __expf(m_r[0] - mn0);
        const float alpha1 = __expf(m_r[1] - mn1);
        m_r[0] = mn0; m_r[1] = mn1;
        float sum0 = 0.f, sum1 = 0.f;
#pragma unroll
        for (int nj = 0; nj < 8; nj++) {
            s[nj][0] = __expf(s[nj][0] - mn0); sum0 += s[nj][0];
            s[nj][1] = __expf(s[nj][1] - mn0); sum0 += s[nj][1];
            s[nj][2] = __expf(s[nj][2] - mn1); sum1 += s[nj][2];
            s[nj][3] = __expf(s[nj][3] - mn1); sum1 += s[nj][3];
        }
        sum0 += __shfl_xor_sync(0xffffffffu, sum0, 1);
        sum0 += __shfl_xor_sync(0xffffffffu, sum0, 2);
        sum1 += __shfl_xor_sync(0xffffffffu, sum1, 1);
        sum1 += __shfl_xor_sync(0xffffffffu, sum1, 2);
        l_r[0] = l_r[0] * alpha0 + sum0;
        l_r[1] = l_r[1] * alpha1 + sum1;
#pragma unroll
        for (int g = 0; g < 8; g++) {
            o[g][0] *= alpha0; o[g][1] *= alpha0;
            o[g][2] *= alpha1; o[g][3] *= alpha1;
        }

        // ---- P fragments (fp16) ----
        uint32_t pa[4][4];
#pragma unroll
        for (int t = 0; t < 4; t++) {
            pa[t][0] = packh(s[2*t][0], s[2*t][1]);
            pa[t][1] = packh(s[2*t][2], s[2*t][3]);
            pa[t][2] = packh(s[2*t+1][0], s[2*t+1][1]);
            pa[t][3] = packh(s[2*t+1][2], s[2*t+1][3]);
        }

        // ---- O += P V (fp16) ----
#pragma unroll
        for (int t = 0; t < 4; t++) {
#pragma unroll
            for (int g = 0; g < 4; g++) {
                const uint32_t vr = (uint32_t)(16 * t) + vRowBase;
                const uint32_t vc = (uint32_t)(g * 32) + vColPart;
                const uint32_t voff = vr * 128 + (vc ^ ((vr & 7) << 4));
                uint32_t vh4[4];
                ldsm_x4_t(vh4, sVH + voff);
                mma_f16(o[2*g],   pa[t], vh4[0], vh4[1]);
                mma_f16(o[2*g+1], pa[t], vh4[2], vh4[3]);
            }
        }
    }

    // ---- epilogue: O/l * hw -> fp16 ao ----
    const int er = lane >> 2;
    const int ec = (lane & 3) * 2;
    const float inv0 = hw / l_r[0];
    const float inv1 = hw / l_r[1];
    const int r0 = q0 + wid * 16 + er;
#pragma unroll
    for (int g = 0; g < 8; g++) {
        const int d = h * HD + g * 8 + ec;
        const size_t i0 = (size_t)(b * SEQ + r0) * DIMC + d;
        const size_t i1 = (size_t)(b * SEQ + r0 + 8) * DIMC + d;
        *(uint32_t*)&aoh[i0] = packh(o[g][0] * inv0, o[g][1] * inv0);
        *(uint32_t*)&aoh[i1] = packh(o[g][2] * inv1, o[g][3] * inv1);
    }
}

// ===========================================================================
extern "C" void kernel_launch(void* const* d_in, const int* in_sizes, int n_in,
                              void* d_out, int out_size)
{
    const float* x      = (const float*)d_in[0];
    const float* w_qkv  = (const float*)d_in[1];
    const float* w_proj = (const float*)d_in[2];
    const float* head_w = (const float*)d_in[3];
    float* out = (float*)d_out;

    __half *xh, *wqh, *wph, *qh, *aoh;
    cudaGetSymbolAddress((void**)&xh,  g_xh);
    cudaGetSymbolAddress((void**)&wqh, g_wqh);
    cudaGetSymbolAddress((void**)&wph, g_wph);
    cudaGetSymbolAddress((void**)&qh,  g_qh);
    cudaGetSymbolAddress((void**)&aoh, g_aoh);

    cudaFuncSetAttribute(gemm_half, cudaFuncAttributeMaxDynamicSharedMemorySize, GEMM_SMEM);
    cudaFuncSetAttribute(flash_half, cudaFuncAttributeMaxDynamicSharedMemorySize, FA_SMEM);

    // 0) fused convert prepass (x, w_qkv, w_proj -> fp16) in ONE launch
    {
        dim3 g0((M_TOT * DIMC) / 1024, 3);   // largest segment sets grid.x
        cvt16_all<<<g0, 256>>>(x, xh, w_qkv, wqh, w_proj, wph);
    }

    // 1) QKV projection -> fp16 qkv
    dim3 g1(QKV_N / 128, M_TOT / 128);
    gemm_half<<<g1, 256, GEMM_SMEM>>>(xh, wqh, nullptr, qh, M_TOT, QKV_N, DIMC);

    // 2) flash attention + head weights -> fp16 ao
    dim3 g2(SEQ / 128, NHEAD, BATCH);
    flash_half<<<g2, 256, FA_SMEM>>>(qh, head_w, aoh);

    // 3) output projection -> fp32 out
    dim3 g3(DIMC / 128, M_TOT / 128);
    gemm_half<<<g3, 256, GEMM_SMEM>>>(aoh, wph, out, nullptr, M_TOT, DIMC, DIMC);
}